// round 12
// baseline (speedup 1.0000x reference)
#include <cuda_runtime.h>
#include <cuda_fp16.h>
#include <mma.h>
#include <cstdint>
#include <cstddef>

using namespace nvcuda;

// x: [16][32][128][128] fp32 == X[2][256][16384] (g, f, p)
// Wq: [512][256], Wkv: [1024][256] (K rows 0..511, V rows 512..1023),
// Wout: [256][512], bout: [256], out: [2][256][16384] fp32
//
//   Xh/Xl = split(X)                     (convert_x)
//   G_g = X_g X_g^T  (symmetric)         (gram_kernel + gram_reduce)
//   Sq_g = Wq @ G_g                      (sq_kernel, 8-row tiles)
//   simp = Sq[h] @ Wk[h]^T (k-split)     (simp_kernel)
//   attn = softmax(0.125 * sum simp)     (softmax_kernel)
//   U_g[h] = attn @ Wv[h]                (u_kernel)
//   W2_g = Wout @ U_g -> fp16 hi/lo      (w2_kernel, 8-row tiles)
//   out_g = W2_g @ X_g + bout            (final_kernel)

#define NSEQ 16384
#define SMS2 40    // fp16 staging stride, 32-half rows (+pad)
#define OVS  136   // fp16 staging stride, 128-half rows (+pad)
#define GSP  32    // gram k-splits
#define FAS  68    // fp32 staging stride (floats), 64-wide tiles

// ------------------------------ scratch ------------------------------------
__device__ __half g_xh  [(size_t)2 * 256 * 16384];      // X hi
__device__ __half g_xl  [(size_t)2 * 256 * 16384];      // X lo
__device__ float  g_gpart[(size_t)2 * GSP * 256 * 256]; // gram partials
__device__ float  g_gram [(size_t)2 * 256 * 256];
__device__ float  g_sq   [(size_t)2 * 512 * 256];
__device__ float  g_simp [(size_t)16 * 4 * 64 * 64];    // sim k-split partials
__device__ float  g_attn [(size_t)16 * 64 * 64];
__device__ float  g_u    [(size_t)2 * 512 * 256];
__device__ __half g_w2_h [(size_t)2 * 256 * 256];
__device__ __half g_w2_l [(size_t)2 * 256 * 256];

__device__ __forceinline__ void split_hl(float v, __half& hi, __half& lo) {
    hi = __float2half_rn(v);
    lo = __float2half_rn(v - __half2float(hi));
}

// ---------------------------------------------------------------------------
// Kernel 0: X fp32 -> Xh/Xl fp16 (same [g][f][p] layout)
// ---------------------------------------------------------------------------
__global__ void __launch_bounds__(256) convert_x(const float* __restrict__ x)
{
    const size_t base = ((size_t)blockIdx.y * 256 + blockIdx.x) * NSEQ;
    const float4* src = reinterpret_cast<const float4*>(x + base);
    uint4* dh = reinterpret_cast<uint4*>(g_xh + base);
    uint4* dl = reinterpret_cast<uint4*>(g_xl + base);
    for (int t = threadIdx.x; t < 2048; t += 256) {
        const float4 v0 = src[2 * t], v1 = src[2 * t + 1];
        __half h[8], l[8];
        split_hl(v0.x, h[0], l[0]); split_hl(v0.y, h[1], l[1]);
        split_hl(v0.z, h[2], l[2]); split_hl(v0.w, h[3], l[3]);
        split_hl(v1.x, h[4], l[4]); split_hl(v1.y, h[5], l[5]);
        split_hl(v1.z, h[6], l[6]); split_hl(v1.w, h[7], l[7]);
        dh[t] = *reinterpret_cast<uint4*>(h);
        dl[t] = *reinterpret_cast<uint4*>(l);
    }
}

// ---------------------------------------------------------------------------
// Kernel 1: gram partials (symmetric). blockIdx.y: 0->(0,0), 1->(1,0), 2->(1,1).
// 128x128 tile, contraction over 512 p per k-split, hi/lo 3-term wmma.
// ---------------------------------------------------------------------------
__global__ void __launch_bounds__(256) gram_kernel()
{
    __shared__ __align__(32) __half sAh[128 * SMS2];
    __shared__ __align__(32) __half sAl[128 * SMS2];
    __shared__ __align__(32) __half sBh[128 * SMS2];
    __shared__ __align__(32) __half sBl[128 * SMS2];

    const int ks = blockIdx.x;                    // 0..GSP-1
    const int y  = blockIdx.y;                    // 0..2
    const int g  = blockIdx.z;
    const int tm = (y >= 1), tn = (y == 2);
    const bool diag = (tm == tn);
    const int p0 = ks * 512;

    const __half* Xh = g_xh + (size_t)g * 256 * NSEQ;
    const __half* Xl = g_xl + (size_t)g * 256 * NSEQ;

    const int tid = threadIdx.x;
    const int wid = tid >> 5;
    const int wm = wid >> 2, wn = wid & 3;

    wmma::fragment<wmma::accumulator, 16, 16, 16, float> acc[4][2];
#pragma unroll
    for (int mi = 0; mi < 4; ++mi)
#pragma unroll
        for (int ni = 0; ni < 2; ++ni) wmma::fill_fragment(acc[mi][ni], 0.0f);

    const __half* pBh = diag ? sAh : sBh;
    const __half* pBl = diag ? sAl : sBl;

#pragma unroll 1
    for (int pc = 0; pc < 512; pc += 32) {
        __syncthreads();
#pragma unroll
        for (int it = 0; it < 2; ++it) {
            const int idx = tid + it * 256;       // 0..511
            const int row = idx >> 2, c4 = idx & 3;
            const size_t ga = (size_t)(tm * 128 + row) * NSEQ + p0 + pc + c4 * 8;
            const int    so = row * SMS2 + c4 * 8;
            *reinterpret_cast<uint4*>(&sAh[so]) = *reinterpret_cast<const uint4*>(Xh + ga);
            *reinterpret_cast<uint4*>(&sAl[so]) = *reinterpret_cast<const uint4*>(Xl + ga);
            if (!diag) {
                const size_t gb = (size_t)(tn * 128 + row) * NSEQ + p0 + pc + c4 * 8;
                *reinterpret_cast<uint4*>(&sBh[so]) = *reinterpret_cast<const uint4*>(Xh + gb);
                *reinterpret_cast<uint4*>(&sBl[so]) = *reinterpret_cast<const uint4*>(Xl + gb);
            }
        }
        __syncthreads();

#pragma unroll
        for (int k2 = 0; k2 < 2; ++k2) {
            wmma::fragment<wmma::matrix_a, 16, 16, 16, __half, wmma::row_major> fah[4], fal[4];
            wmma::fragment<wmma::matrix_b, 16, 16, 16, __half, wmma::col_major> fbh[2], fbl[2];
#pragma unroll
            for (int mi = 0; mi < 4; ++mi) {
                const int ro = (wm * 64 + mi * 16) * SMS2 + k2 * 16;
                wmma::load_matrix_sync(fah[mi], &sAh[ro], SMS2);
                wmma::load_matrix_sync(fal[mi], &sAl[ro], SMS2);
            }
#pragma unroll
            for (int ni = 0; ni < 2; ++ni) {
                const int ro = (wn * 32 + ni * 16) * SMS2 + k2 * 16;
                wmma::load_matrix_sync(fbh[ni], &pBh[ro], SMS2);
                wmma::load_matrix_sync(fbl[ni], &pBl[ro], SMS2);
            }
#pragma unroll
            for (int mi = 0; mi < 4; ++mi)
#pragma unroll
                for (int ni = 0; ni < 2; ++ni) {
                    wmma::mma_sync(acc[mi][ni], fah[mi], fbh[ni], acc[mi][ni]);
                    wmma::mma_sync(acc[mi][ni], fah[mi], fbl[ni], acc[mi][ni]);
                    wmma::mma_sync(acc[mi][ni], fal[mi], fbh[ni], acc[mi][ni]);
                }
        }
    }

    float* P = g_gpart + (size_t)(g * GSP + ks) * 65536;
#pragma unroll
    for (int mi = 0; mi < 4; ++mi)
#pragma unroll
        for (int ni = 0; ni < 2; ++ni) {
            const int rb = tm * 128 + wm * 64 + mi * 16;
            const int cb = tn * 128 + wn * 32 + ni * 16;
            wmma::store_matrix_sync(P + (size_t)rb * 256 + cb, acc[mi][ni],
                                    256, wmma::mem_row_major);
            if (tm != tn)   // mirror into upper-right block (transpose)
                wmma::store_matrix_sync(P + (size_t)cb * 256 + rb, acc[mi][ni],
                                        256, wmma::mem_col_major);
        }
}

// ---------------------------------------------------------------------------
// Kernel 2: reduce gram partials.
// ---------------------------------------------------------------------------
__global__ void __launch_bounds__(256) gram_reduce()
{
    const int a = blockIdx.x, g = blockIdx.y, b = threadIdx.x;
    float s = 0.f;
#pragma unroll 8
    for (int ks = 0; ks < GSP; ++ks)
        s += g_gpart[((size_t)(g * GSP + ks) * 256 + a) * 256 + b];
    g_gram[((size_t)g * 256 + a) * 256 + b] = s;
}

// ---------------------------------------------------------------------------
// Kernel 3: Sq_g = Wq @ G_g   (512x256 per group, K=256, fp32)
// 8-row m-tiles: block stages 8 Wq rows in smem, each thread owns column n
// and accumulates 8 outputs -> G traffic amortized 8x.
// ---------------------------------------------------------------------------
__global__ void __launch_bounds__(256) sq_kernel(const float* __restrict__ Wq)
{
    __shared__ float s_w[8 * 256];
    const int m0 = blockIdx.x * 8, g = blockIdx.y, n = threadIdx.x;
    const float* G = g_gram + (size_t)g * 65536;

#pragma unroll
    for (int r = 0; r < 8; ++r)
        s_w[r * 256 + n] = Wq[(size_t)(m0 + r) * 256 + n];
    __syncthreads();

    float acc[8] = {};
#pragma unroll 4
    for (int k = 0; k < 256; ++k) {
        const float gv = G[k * 256 + n];
#pragma unroll
        for (int r = 0; r < 8; ++r)
            acc[r] = fmaf(s_w[r * 256 + k], gv, acc[r]);
    }
#pragma unroll
    for (int r = 0; r < 8; ++r)
        g_sq[((size_t)g * 512 + m0 + r) * 256 + n] = acc[r];
}

// ---------------------------------------------------------------------------
// Kernel 4: sim partials. grid (4 ksplit, 16 gh). 64x64 out, K=64 per block.
// ---------------------------------------------------------------------------
__global__ void __launch_bounds__(256) simp_kernel(const float* __restrict__ Wkv)
{
    __shared__ __align__(16) float s_q[64 * FAS];
    __shared__ __align__(16) float s_k[64 * FAS];

    const int ks = blockIdx.x, gh = blockIdx.y;
    const int g = gh >> 3, h = gh & 7;
    const int tid = threadIdx.x;

    const float* SQ = g_sq + ((size_t)g * 512 + h * 64) * 256 + ks * 64;
    const float* WK = Wkv + (size_t)(h * 64) * 256 + ks * 64;

#pragma unroll
    for (int it = 0; it < 4; ++it) {
        const int idx = tid + it * 256;          // 0..1023
        const int row = idx >> 4, c4 = idx & 15;
        *reinterpret_cast<float4*>(&s_q[row * FAS + c4 * 4]) =
            *reinterpret_cast<const float4*>(SQ + (size_t)row * 256 + c4 * 4);
        *reinterpret_cast<float4*>(&s_k[row * FAS + c4 * 4]) =
            *reinterpret_cast<const float4*>(WK + (size_t)row * 256 + c4 * 4);
    }
    __syncthreads();

    const int i0 = (tid >> 4) * 4, j0 = (tid & 15) * 4;
    float acc[4][4] = {};
#pragma unroll
    for (int k = 0; k < 64; k += 4) {
        float4 qv[4], kv[4];
#pragma unroll
        for (int a = 0; a < 4; ++a) {
            qv[a] = *reinterpret_cast<const float4*>(&s_q[(i0 + a) * FAS + k]);
            kv[a] = *reinterpret_cast<const float4*>(&s_k[(j0 + a) * FAS + k]);
        }
#pragma unroll
        for (int a = 0; a < 4; ++a)
#pragma unroll
            for (int b = 0; b < 4; ++b)
                acc[a][b] += qv[a].x * kv[b].x + qv[a].y * kv[b].y
                           + qv[a].z * kv[b].z + qv[a].w * kv[b].w;
    }

    float* P = g_simp + (size_t)(gh * 4 + ks) * 4096;
#pragma unroll
    for (int a = 0; a < 4; ++a)
        *reinterpret_cast<float4*>(&P[(i0 + a) * 64 + j0]) =
            make_float4(acc[a][0], acc[a][1], acc[a][2], acc[a][3]);
}

// ---------------------------------------------------------------------------
// Kernel 5: reduce sim partials + scale + softmax. grid (64, 16), 64 thr.
// ---------------------------------------------------------------------------
__global__ void __launch_bounds__(64) softmax_kernel()
{
    const int i  = blockIdx.x;
    const int gh = blockIdx.y;
    const int j  = threadIdx.x;

    float v = 0.f;
#pragma unroll
    for (int ks = 0; ks < 4; ++ks)
        v += g_simp[(size_t)(gh * 4 + ks) * 4096 + i * 64 + j];
    v *= 0.125f;

    __shared__ float s[64];
    __shared__ float red;
    s[j] = v;
    __syncthreads();
    if (j == 0) {
        float m = s[0];
        for (int t = 1; t < 64; ++t) m = fmaxf(m, s[t]);
        red = m;
    }
    __syncthreads();
    const float e = __expf(v - red);
    s[j] = e;
    __syncthreads();
    if (j == 0) {
        float su = 0.f;
        for (int t = 0; t < 64; ++t) su += s[t];
        red = su;
    }
    __syncthreads();
    g_attn[(size_t)gh * 4096 + i * 64 + j] = e / red;
}

// ---------------------------------------------------------------------------
// Kernel 6: U = attn @ Wv. grid (4 ftile, 16 gh). 64x64 out, K=64.
// ---------------------------------------------------------------------------
__global__ void __launch_bounds__(256) u_kernel(const float* __restrict__ Wkv)
{
    __shared__ __align__(16) float s_a[64 * FAS];
    __shared__ __align__(16) float s_w[64 * FAS];

    const int ft = blockIdx.x, gh = blockIdx.y;
    const int g = gh >> 3, h = gh & 7;
    const int tid = threadIdx.x;

    const float* A  = g_attn + (size_t)gh * 4096;
    const float* WV = Wkv + (size_t)(512 + h * 64) * 256 + ft * 64;

#pragma unroll
    for (int it = 0; it < 4; ++it) {
        const int idx = tid + it * 256;
        const int row = idx >> 4, c4 = idx & 15;
        *reinterpret_cast<float4*>(&s_a[row * FAS + c4 * 4]) =
            *reinterpret_cast<const float4*>(A + (size_t)row * 64 + c4 * 4);
        *reinterpret_cast<float4*>(&s_w[row * FAS + c4 * 4]) =
            *reinterpret_cast<const float4*>(WV + (size_t)row * 256 + c4 * 4);
    }
    __syncthreads();

    const int i0 = (tid >> 4) * 4, f0 = (tid & 15) * 4;
    float acc[4][4] = {};
#pragma unroll
    for (int j = 0; j < 64; ++j) {
        const float4 wv = *reinterpret_cast<const float4*>(&s_w[j * FAS + f0]);
        float av[4];
#pragma unroll
        for (int a = 0; a < 4; ++a) av[a] = s_a[(i0 + a) * FAS + j];
#pragma unroll
        for (int a = 0; a < 4; ++a) {
            acc[a][0] += av[a] * wv.x; acc[a][1] += av[a] * wv.y;
            acc[a][2] += av[a] * wv.z; acc[a][3] += av[a] * wv.w;
        }
    }

    float* U = g_u + ((size_t)g * 512 + h * 64) * 256 + ft * 64;
#pragma unroll
    for (int a = 0; a < 4; ++a)
        *reinterpret_cast<float4*>(&U[(size_t)(i0 + a) * 256 + f0]) =
            make_float4(acc[a][0], acc[a][1], acc[a][2], acc[a][3]);
}

// ---------------------------------------------------------------------------
// Kernel 7: W2_g = Wout @ U_g -> fp16 hi/lo (256x256 per group, K=512)
// 8-row m-tiles like sq_kernel.
// ---------------------------------------------------------------------------
__global__ void __launch_bounds__(256) w2_kernel(const float* __restrict__ Wout)
{
    __shared__ float s_w[8 * 512];
    const int m0 = blockIdx.x * 8, g = blockIdx.y, n = threadIdx.x;
    const float* Ug = g_u + (size_t)g * 512 * 256;

#pragma unroll
    for (int r = 0; r < 8; ++r) {
        s_w[r * 512 + n]       = Wout[(size_t)(m0 + r) * 512 + n];
        s_w[r * 512 + 256 + n] = Wout[(size_t)(m0 + r) * 512 + 256 + n];
    }
    __syncthreads();

    float acc[8] = {};
#pragma unroll 4
    for (int c = 0; c < 512; ++c) {
        const float uv = Ug[(size_t)c * 256 + n];
#pragma unroll
        for (int r = 0; r < 8; ++r)
            acc[r] = fmaf(s_w[r * 512 + c], uv, acc[r]);
    }
#pragma unroll
    for (int r = 0; r < 8; ++r) {
        __half hv, lv;
        split_hl(acc[r], hv, lv);
        g_w2_h[((size_t)g * 256 + m0 + r) * 256 + n] = hv;
        g_w2_l[((size_t)g * 256 + m0 + r) * 256 + n] = lv;
    }
}

// ---------------------------------------------------------------------------
// Kernel 8: out_g = W2_g @ X_g + bout.  M=256, N=16384, K=256.
// ---------------------------------------------------------------------------
__global__ void __launch_bounds__(256) final_kernel(const float* __restrict__ bout,
                                                    float* __restrict__ out)
{
    __shared__ __align__(32) __half sAh[128 * SMS2];
    __shared__ __align__(32) __half sAl[128 * SMS2];
    __shared__ __align__(32) __half sBh[32 * OVS];
    __shared__ __align__(32) __half sBl[32 * OVS];
    __shared__ __align__(32) float  brep[128 * 16];

    const int tid = threadIdx.x;
    const int wid = tid >> 5;
    const int wm = wid >> 2, wn = wid & 3;
    const int p0 = blockIdx.x * 128;
    const int m0 = blockIdx.y * 128;
    const int g  = blockIdx.z;

    const __half* Ah = g_w2_h + (size_t)g * 65536;
    const __half* Al = g_w2_l + (size_t)g * 65536;
    const __half* Xh = g_xh + (size_t)g * 256 * NSEQ;
    const __half* Xl = g_xl + (size_t)g * 256 * NSEQ;

    for (int r = tid; r < 128; r += 256) {
        const float bv = bout[m0 + r];
#pragma unroll
        for (int c = 0; c < 16; ++c) brep[r * 16 + c] = bv;
    }
    __syncthreads();

    wmma::fragment<wmma::accumulator, 16, 16, 16, float> acc[4][2];
#pragma unroll
    for (int mi = 0; mi < 4; ++mi)
#pragma unroll
        for (int ni = 0; ni < 2; ++ni)
            wmma::load_matrix_sync(acc[mi][ni],
                                   &brep[(wm * 64 + mi * 16) * 16], 16,
                                   wmma::mem_row_major);

#pragma unroll 1
    for (int kk = 0; kk < 256; kk += 32) {
        __syncthreads();
#pragma unroll
        for (int it = 0; it < 2; ++it) {
            const int idx = tid + it * 256;
            const int row = idx >> 2, c4 = idx & 3;
            const size_t go = (size_t)(m0 + row) * 256 + kk + c4 * 8;
            const int    so = row * SMS2 + c4 * 8;
            *reinterpret_cast<uint4*>(&sAh[so]) = *reinterpret_cast<const uint4*>(Ah + go);
            *reinterpret_cast<uint4*>(&sAl[so]) = *reinterpret_cast<const uint4*>(Al + go);
        }
#pragma unroll
        for (int it = 0; it < 2; ++it) {
            const int idx = tid + it * 256;      // 0..511
            const int row = idx >> 4, c8 = idx & 15;
            const size_t go = (size_t)(kk + row) * NSEQ + p0 + c8 * 8;
            const int    so = row * OVS + c8 * 8;
            *reinterpret_cast<uint4*>(&sBh[so]) = *reinterpret_cast<const uint4*>(Xh + go);
            *reinterpret_cast<uint4*>(&sBl[so]) = *reinterpret_cast<const uint4*>(Xl + go);
        }
        __syncthreads();

#pragma unroll
        for (int k2 = 0; k2 < 2; ++k2) {
            wmma::fragment<wmma::matrix_a, 16, 16, 16, __half, wmma::row_major> fah[4], fal[4];
            wmma::fragment<wmma::matrix_b, 16, 16, 16, __half, wmma::row_major> fbh[2], fbl[2];
#pragma unroll
            for (int mi = 0; mi < 4; ++mi) {
                const int ro = (wm * 64 + mi * 16) * SMS2 + k2 * 16;
                wmma::load_matrix_sync(fah[mi], &sAh[ro], SMS2);
                wmma::load_matrix_sync(fal[mi], &sAl[ro], SMS2);
            }
#pragma unroll
            for (int ni = 0; ni < 2; ++ni) {
                const int co = (k2 * 16) * OVS + wn * 32 + ni * 16;
                wmma::load_matrix_sync(fbh[ni], &sBh[co], OVS);
                wmma::load_matrix_sync(fbl[ni], &sBl[co], OVS);
            }
#pragma unroll
            for (int mi = 0; mi < 4; ++mi)
#pragma unroll
                for (int ni = 0; ni < 2; ++ni) {
                    wmma::mma_sync(acc[mi][ni], fah[mi], fbh[ni], acc[mi][ni]);
                    wmma::mma_sync(acc[mi][ni], fah[mi], fbl[ni], acc[mi][ni]);
                    wmma::mma_sync(acc[mi][ni], fal[mi], fbh[ni], acc[mi][ni]);
                }
        }
    }

    float* C = out + (size_t)g * 256 * NSEQ;
#pragma unroll
    for (int mi = 0; mi < 4; ++mi)
#pragma unroll
        for (int ni = 0; ni < 2; ++ni)
            wmma::store_matrix_sync(
                C + (size_t)(m0 + wm * 64 + mi * 16) * NSEQ + p0 + wn * 32 + ni * 16,
                acc[mi][ni], NSEQ, wmma::mem_row_major);
}

// ---------------------------------------------------------------------------
extern "C" void kernel_launch(void* const* d_in, const int* in_sizes, int n_in,
                              void* d_out, int out_size)
{
    const float* x    = (const float*)d_in[0];
    const float* Wq   = (const float*)d_in[1];
    const float* Wkv  = (const float*)d_in[2];
    const float* Wout = (const float*)d_in[3];
    const float* bout = (const float*)d_in[4];
    float* out = (float*)d_out;
    (void)in_sizes; (void)n_in; (void)out_size;

    convert_x   <<<dim3(256, 2), 256>>>(x);
    gram_kernel <<<dim3(GSP, 3, 2), 256>>>();
    gram_reduce <<<dim3(256, 2), 256>>>();
    sq_kernel   <<<dim3(64, 2), 256>>>(Wq);
    simp_kernel <<<dim3(4, 16), 256>>>(Wkv);
    softmax_kernel<<<dim3(64, 16), 64>>>();
    u_kernel    <<<dim3(4, 16), 256>>>(Wkv);
    w2_kernel   <<<dim3(32, 2), 256>>>(Wout);
    final_kernel<<<dim3(NSEQ / 128, 2, 2), 256>>>(bout, out);
}

// round 13
// speedup vs baseline: 1.2283x; 1.2283x over previous
#include <cuda_runtime.h>
#include <cuda_fp16.h>
#include <mma.h>
#include <cstdint>
#include <cstddef>

using namespace nvcuda;

// x: [16][32][128][128] fp32 == X[2][256][16384] (g, f, p)
// Wq: [512][256], Wkv: [1024][256] (K rows 0..511, V rows 512..1023),
// Wout: [256][512], bout: [256], out: [2][256][16384] fp32
//
//   Xh/Xl = split(X)                     (convert_x)
//   G_g = X_g X_g^T  (symmetric)         (gram_kernel + gram_reduce)
//   Sq_g = Wq @ G_g                      (sq_kernel, 2-row tiles)
//   simp = Sq[h] @ Wk[h]^T (k-split)     (simp_kernel)
//   attn = softmax(0.125 * sum simp)     (softmax_kernel)
//   U_g[h] = attn @ Wv[h]                (u_kernel)
//   W2_g = Wout @ U_g -> fp16 hi/lo      (w2_kernel, 2-row tiles)
//   out_g = W2_g @ X_g + bout            (final_kernel)

#define NSEQ 16384
#define SMS2 40    // fp16 staging stride, 32-half rows (+pad)
#define OVS  136   // fp16 staging stride, 128-half rows (+pad)
#define GSP  32    // gram k-splits
#define FAS  68    // fp32 staging stride (floats), 64-wide tiles

// ------------------------------ scratch ------------------------------------
__device__ __half g_xh  [(size_t)2 * 256 * 16384];      // X hi
__device__ __half g_xl  [(size_t)2 * 256 * 16384];      // X lo
__device__ float  g_gpart[(size_t)2 * GSP * 256 * 256]; // gram partials
__device__ float  g_gram [(size_t)2 * 256 * 256];
__device__ float  g_sq   [(size_t)2 * 512 * 256];
__device__ float  g_simp [(size_t)16 * 4 * 64 * 64];    // sim k-split partials
__device__ float  g_attn [(size_t)16 * 64 * 64];
__device__ float  g_u    [(size_t)2 * 512 * 256];
__device__ __half g_w2_h [(size_t)2 * 256 * 256];
__device__ __half g_w2_l [(size_t)2 * 256 * 256];

__device__ __forceinline__ void split_hl(float v, __half& hi, __half& lo) {
    hi = __float2half_rn(v);
    lo = __float2half_rn(v - __half2float(hi));
}

// ---------------------------------------------------------------------------
// Kernel 0: X fp32 -> Xh/Xl fp16 (same [g][f][p] layout)
// ---------------------------------------------------------------------------
__global__ void __launch_bounds__(256) convert_x(const float* __restrict__ x)
{
    const size_t base = ((size_t)blockIdx.y * 256 + blockIdx.x) * NSEQ;
    const float4* src = reinterpret_cast<const float4*>(x + base);
    uint4* dh = reinterpret_cast<uint4*>(g_xh + base);
    uint4* dl = reinterpret_cast<uint4*>(g_xl + base);
    for (int t = threadIdx.x; t < 2048; t += 256) {
        const float4 v0 = src[2 * t], v1 = src[2 * t + 1];
        __half h[8], l[8];
        split_hl(v0.x, h[0], l[0]); split_hl(v0.y, h[1], l[1]);
        split_hl(v0.z, h[2], l[2]); split_hl(v0.w, h[3], l[3]);
        split_hl(v1.x, h[4], l[4]); split_hl(v1.y, h[5], l[5]);
        split_hl(v1.z, h[6], l[6]); split_hl(v1.w, h[7], l[7]);
        dh[t] = *reinterpret_cast<uint4*>(h);
        dl[t] = *reinterpret_cast<uint4*>(l);
    }
}

// ---------------------------------------------------------------------------
// Kernel 1: gram partials (symmetric), register-prefetch double buffered.
// blockIdx.y: 0->(0,0), 1->(1,0), 2->(1,1). 128x128 tile, 512 p per k-split.
// ---------------------------------------------------------------------------
__global__ void __launch_bounds__(256) gram_kernel()
{
    __shared__ __align__(32) __half sAh[128 * SMS2];
    __shared__ __align__(32) __half sAl[128 * SMS2];
    __shared__ __align__(32) __half sBh[128 * SMS2];
    __shared__ __align__(32) __half sBl[128 * SMS2];

    const int ks = blockIdx.x;                    // 0..GSP-1
    const int y  = blockIdx.y;                    // 0..2
    const int g  = blockIdx.z;
    const int tm = (y >= 1), tn = (y == 2);
    const bool diag = (tm == tn);
    const int p0 = ks * 512;

    const __half* Xh = g_xh + (size_t)g * 256 * NSEQ;
    const __half* Xl = g_xl + (size_t)g * 256 * NSEQ;

    const int tid = threadIdx.x;
    const int wid = tid >> 5;
    const int wm = wid >> 2, wn = wid & 3;

    const int lrow = (tid + 0) >> 2;          // rows for it=0 / it=1
    const int lc4  = tid & 3;
    const int rows[2] = { (tid) >> 2, (tid + 256) >> 2 };
    (void)lrow;

    wmma::fragment<wmma::accumulator, 16, 16, 16, float> acc[4][2];
#pragma unroll
    for (int mi = 0; mi < 4; ++mi)
#pragma unroll
        for (int ni = 0; ni < 2; ++ni) wmma::fill_fragment(acc[mi][ni], 0.0f);

    const __half* pBh = diag ? sAh : sBh;
    const __half* pBl = diag ? sAl : sBl;

    uint4 rAh[2], rAl[2], rBh[2], rBl[2];

    // prologue: load chunk 0 into registers
#pragma unroll
    for (int it = 0; it < 2; ++it) {
        const size_t ga = (size_t)(tm * 128 + rows[it]) * NSEQ + p0 + lc4 * 8;
        rAh[it] = *reinterpret_cast<const uint4*>(Xh + ga);
        rAl[it] = *reinterpret_cast<const uint4*>(Xl + ga);
        if (!diag) {
            const size_t gb = (size_t)(tn * 128 + rows[it]) * NSEQ + p0 + lc4 * 8;
            rBh[it] = *reinterpret_cast<const uint4*>(Xh + gb);
            rBl[it] = *reinterpret_cast<const uint4*>(Xl + gb);
        }
    }

#pragma unroll 1
    for (int pc = 0; pc < 512; pc += 32) {
        __syncthreads();   // previous MMA done consuming smem
#pragma unroll
        for (int it = 0; it < 2; ++it) {
            const int so = rows[it] * SMS2 + lc4 * 8;
            *reinterpret_cast<uint4*>(&sAh[so]) = rAh[it];
            *reinterpret_cast<uint4*>(&sAl[so]) = rAl[it];
            if (!diag) {
                *reinterpret_cast<uint4*>(&sBh[so]) = rBh[it];
                *reinterpret_cast<uint4*>(&sBl[so]) = rBl[it];
            }
        }
        __syncthreads();   // stores visible

        // prefetch next chunk into registers (overlaps with MMA below)
        if (pc + 32 < 512) {
#pragma unroll
            for (int it = 0; it < 2; ++it) {
                const size_t ga = (size_t)(tm * 128 + rows[it]) * NSEQ
                                + p0 + pc + 32 + lc4 * 8;
                rAh[it] = *reinterpret_cast<const uint4*>(Xh + ga);
                rAl[it] = *reinterpret_cast<const uint4*>(Xl + ga);
                if (!diag) {
                    const size_t gb = (size_t)(tn * 128 + rows[it]) * NSEQ
                                    + p0 + pc + 32 + lc4 * 8;
                    rBh[it] = *reinterpret_cast<const uint4*>(Xh + gb);
                    rBl[it] = *reinterpret_cast<const uint4*>(Xl + gb);
                }
            }
        }

#pragma unroll
        for (int k2 = 0; k2 < 2; ++k2) {
            wmma::fragment<wmma::matrix_a, 16, 16, 16, __half, wmma::row_major> fah[4], fal[4];
            wmma::fragment<wmma::matrix_b, 16, 16, 16, __half, wmma::col_major> fbh[2], fbl[2];
#pragma unroll
            for (int mi = 0; mi < 4; ++mi) {
                const int ro = (wm * 64 + mi * 16) * SMS2 + k2 * 16;
                wmma::load_matrix_sync(fah[mi], &sAh[ro], SMS2);
                wmma::load_matrix_sync(fal[mi], &sAl[ro], SMS2);
            }
#pragma unroll
            for (int ni = 0; ni < 2; ++ni) {
                const int ro = (wn * 32 + ni * 16) * SMS2 + k2 * 16;
                wmma::load_matrix_sync(fbh[ni], &pBh[ro], SMS2);
                wmma::load_matrix_sync(fbl[ni], &pBl[ro], SMS2);
            }
#pragma unroll
            for (int mi = 0; mi < 4; ++mi)
#pragma unroll
                for (int ni = 0; ni < 2; ++ni) {
                    wmma::mma_sync(acc[mi][ni], fah[mi], fbh[ni], acc[mi][ni]);
                    wmma::mma_sync(acc[mi][ni], fah[mi], fbl[ni], acc[mi][ni]);
                    wmma::mma_sync(acc[mi][ni], fal[mi], fbh[ni], acc[mi][ni]);
                }
        }
    }

    float* P = g_gpart + (size_t)(g * GSP + ks) * 65536;
#pragma unroll
    for (int mi = 0; mi < 4; ++mi)
#pragma unroll
        for (int ni = 0; ni < 2; ++ni) {
            const int rb = tm * 128 + wm * 64 + mi * 16;
            const int cb = tn * 128 + wn * 32 + ni * 16;
            wmma::store_matrix_sync(P + (size_t)rb * 256 + cb, acc[mi][ni],
                                    256, wmma::mem_row_major);
            if (tm != tn)   // mirror into upper-right block (transpose)
                wmma::store_matrix_sync(P + (size_t)cb * 256 + rb, acc[mi][ni],
                                        256, wmma::mem_col_major);
        }
}

// ---------------------------------------------------------------------------
// Kernel 2: reduce gram partials.
// ---------------------------------------------------------------------------
__global__ void __launch_bounds__(256) gram_reduce()
{
    const int a = blockIdx.x, g = blockIdx.y, b = threadIdx.x;
    float s = 0.f;
#pragma unroll 8
    for (int ks = 0; ks < GSP; ++ks)
        s += g_gpart[((size_t)(g * GSP + ks) * 256 + a) * 256 + b];
    g_gram[((size_t)g * 256 + a) * 256 + b] = s;
}

// ---------------------------------------------------------------------------
// Kernel 3: Sq_g = Wq @ G_g  (512x256 per group, K=256, fp32)
// 2-row tiles, grid (256, 2): coalesced G rows amortized 2x, 512 blocks.
// ---------------------------------------------------------------------------
__global__ void __launch_bounds__(256) sq_kernel(const float* __restrict__ Wq)
{
    __shared__ float s_w[2 * 256];
    const int m0 = blockIdx.x * 2, g = blockIdx.y, n = threadIdx.x;
    const float* G = g_gram + (size_t)g * 65536;

    s_w[n]       = Wq[(size_t)m0 * 256 + n];
    s_w[256 + n] = Wq[(size_t)(m0 + 1) * 256 + n];
    __syncthreads();

    float a0 = 0.f, a1 = 0.f;
#pragma unroll 8
    for (int k = 0; k < 256; ++k) {
        const float gv = G[k * 256 + n];
        a0 = fmaf(s_w[k], gv, a0);
        a1 = fmaf(s_w[256 + k], gv, a1);
    }
    g_sq[((size_t)g * 512 + m0) * 256 + n]     = a0;
    g_sq[((size_t)g * 512 + m0 + 1) * 256 + n] = a1;
}

// ---------------------------------------------------------------------------
// Kernel 4: sim partials. grid (4 ksplit, 16 gh). 64x64 out, K=64 per block.
// ---------------------------------------------------------------------------
__global__ void __launch_bounds__(256) simp_kernel(const float* __restrict__ Wkv)
{
    __shared__ __align__(16) float s_q[64 * FAS];
    __shared__ __align__(16) float s_k[64 * FAS];

    const int ks = blockIdx.x, gh = blockIdx.y;
    const int g = gh >> 3, h = gh & 7;
    const int tid = threadIdx.x;

    const float* SQ = g_sq + ((size_t)g * 512 + h * 64) * 256 + ks * 64;
    const float* WK = Wkv + (size_t)(h * 64) * 256 + ks * 64;

#pragma unroll
    for (int it = 0; it < 4; ++it) {
        const int idx = tid + it * 256;          // 0..1023
        const int row = idx >> 4, c4 = idx & 15;
        *reinterpret_cast<float4*>(&s_q[row * FAS + c4 * 4]) =
            *reinterpret_cast<const float4*>(SQ + (size_t)row * 256 + c4 * 4);
        *reinterpret_cast<float4*>(&s_k[row * FAS + c4 * 4]) =
            *reinterpret_cast<const float4*>(WK + (size_t)row * 256 + c4 * 4);
    }
    __syncthreads();

    const int i0 = (tid >> 4) * 4, j0 = (tid & 15) * 4;
    float acc[4][4] = {};
#pragma unroll
    for (int k = 0; k < 64; k += 4) {
        float4 qv[4], kv[4];
#pragma unroll
        for (int a = 0; a < 4; ++a) {
            qv[a] = *reinterpret_cast<const float4*>(&s_q[(i0 + a) * FAS + k]);
            kv[a] = *reinterpret_cast<const float4*>(&s_k[(j0 + a) * FAS + k]);
        }
#pragma unroll
        for (int a = 0; a < 4; ++a)
#pragma unroll
            for (int b = 0; b < 4; ++b)
                acc[a][b] += qv[a].x * kv[b].x + qv[a].y * kv[b].y
                           + qv[a].z * kv[b].z + qv[a].w * kv[b].w;
    }

    float* P = g_simp + (size_t)(gh * 4 + ks) * 4096;
#pragma unroll
    for (int a = 0; a < 4; ++a)
        *reinterpret_cast<float4*>(&P[(i0 + a) * 64 + j0]) =
            make_float4(acc[a][0], acc[a][1], acc[a][2], acc[a][3]);
}

// ---------------------------------------------------------------------------
// Kernel 5: reduce sim partials + scale + softmax. grid (64, 16), 64 thr.
// ---------------------------------------------------------------------------
__global__ void __launch_bounds__(64) softmax_kernel()
{
    const int i  = blockIdx.x;
    const int gh = blockIdx.y;
    const int j  = threadIdx.x;

    float v = 0.f;
#pragma unroll
    for (int ks = 0; ks < 4; ++ks)
        v += g_simp[(size_t)(gh * 4 + ks) * 4096 + i * 64 + j];
    v *= 0.125f;

    __shared__ float s[64];
    __shared__ float red;
    s[j] = v;
    __syncthreads();
    if (j == 0) {
        float m = s[0];
        for (int t = 1; t < 64; ++t) m = fmaxf(m, s[t]);
        red = m;
    }
    __syncthreads();
    const float e = __expf(v - red);
    s[j] = e;
    __syncthreads();
    if (j == 0) {
        float su = 0.f;
        for (int t = 0; t < 64; ++t) su += s[t];
        red = su;
    }
    __syncthreads();
    g_attn[(size_t)gh * 4096 + i * 64 + j] = e / red;
}

// ---------------------------------------------------------------------------
// Kernel 6: U = attn @ Wv. grid (4 ftile, 16 gh). 64x64 out, K=64.
// ---------------------------------------------------------------------------
__global__ void __launch_bounds__(256) u_kernel(const float* __restrict__ Wkv)
{
    __shared__ __align__(16) float s_a[64 * FAS];
    __shared__ __align__(16) float s_w[64 * FAS];

    const int ft = blockIdx.x, gh = blockIdx.y;
    const int g = gh >> 3, h = gh & 7;
    const int tid = threadIdx.x;

    const float* A  = g_attn + (size_t)gh * 4096;
    const float* WV = Wkv + (size_t)(512 + h * 64) * 256 + ft * 64;

#pragma unroll
    for (int it = 0; it < 4; ++it) {
        const int idx = tid + it * 256;
        const int row = idx >> 4, c4 = idx & 15;
        *reinterpret_cast<float4*>(&s_a[row * FAS + c4 * 4]) =
            *reinterpret_cast<const float4*>(A + (size_t)row * 64 + c4 * 4);
        *reinterpret_cast<float4*>(&s_w[row * FAS + c4 * 4]) =
            *reinterpret_cast<const float4*>(WV + (size_t)row * 256 + c4 * 4);
    }
    __syncthreads();

    const int i0 = (tid >> 4) * 4, f0 = (tid & 15) * 4;
    float acc[4][4] = {};
#pragma unroll
    for (int j = 0; j < 64; ++j) {
        const float4 wv = *reinterpret_cast<const float4*>(&s_w[j * FAS + f0]);
        float av[4];
#pragma unroll
        for (int a = 0; a < 4; ++a) av[a] = s_a[(i0 + a) * FAS + j];
#pragma unroll
        for (int a = 0; a < 4; ++a) {
            acc[a][0] += av[a] * wv.x; acc[a][1] += av[a] * wv.y;
            acc[a][2] += av[a] * wv.z; acc[a][3] += av[a] * wv.w;
        }
    }

    float* U = g_u + ((size_t)g * 512 + h * 64) * 256 + ft * 64;
#pragma unroll
    for (int a = 0; a < 4; ++a)
        *reinterpret_cast<float4*>(&U[(size_t)(i0 + a) * 256 + f0]) =
            make_float4(acc[a][0], acc[a][1], acc[a][2], acc[a][3]);
}

// ---------------------------------------------------------------------------
// Kernel 7: W2_g = Wout @ U_g -> fp16 hi/lo (256x256 per group, K=512)
// 2-row tiles, grid (128, 2): 256 blocks.
// ---------------------------------------------------------------------------
__global__ void __launch_bounds__(256) w2_kernel(const float* __restrict__ Wout)
{
    __shared__ float s_w[2 * 512];
    const int m0 = blockIdx.x * 2, g = blockIdx.y, n = threadIdx.x;
    const float* Ug = g_u + (size_t)g * 512 * 256;

    s_w[n]         = Wout[(size_t)m0 * 512 + n];
    s_w[256 + n]   = Wout[(size_t)m0 * 512 + 256 + n];
    s_w[512 + n]   = Wout[(size_t)(m0 + 1) * 512 + n];
    s_w[768 + n]   = Wout[(size_t)(m0 + 1) * 512 + 256 + n];
    __syncthreads();

    float a0 = 0.f, a1 = 0.f;
#pragma unroll 8
    for (int c = 0; c < 512; ++c) {
        const float uv = Ug[(size_t)c * 256 + n];
        a0 = fmaf(s_w[c], uv, a0);
        a1 = fmaf(s_w[512 + c], uv, a1);
    }
    __half h0, l0, h1, l1;
    split_hl(a0, h0, l0);
    split_hl(a1, h1, l1);
    g_w2_h[((size_t)g * 256 + m0) * 256 + n]     = h0;
    g_w2_l[((size_t)g * 256 + m0) * 256 + n]     = l0;
    g_w2_h[((size_t)g * 256 + m0 + 1) * 256 + n] = h1;
    g_w2_l[((size_t)g * 256 + m0 + 1) * 256 + n] = l1;
}

// ---------------------------------------------------------------------------
// Kernel 8: out_g = W2_g @ X_g + bout.  M=256, N=16384, K=256.
// Register-prefetch double buffered.
// ---------------------------------------------------------------------------
__global__ void __launch_bounds__(256) final_kernel(const float* __restrict__ bout,
                                                    float* __restrict__ out)
{
    __shared__ __align__(32) __half sAh[128 * SMS2];
    __shared__ __align__(32) __half sAl[128 * SMS2];
    __shared__ __align__(32) __half sBh[32 * OVS];
    __shared__ __align__(32) __half sBl[32 * OVS];
    __shared__ __align__(32) float  brep[128 * 16];

    const int tid = threadIdx.x;
    const int wid = tid >> 5;
    const int wm = wid >> 2, wn = wid & 3;
    const int p0 = blockIdx.x * 128;
    const int m0 = blockIdx.y * 128;
    const int g  = blockIdx.z;

    const __half* Ah = g_w2_h + (size_t)g * 65536;
    const __half* Al = g_w2_l + (size_t)g * 65536;
    const __half* Xh = g_xh + (size_t)g * 256 * NSEQ;
    const __half* Xl = g_xl + (size_t)g * 256 * NSEQ;

    // load index precompute
    const int arow[2] = { (tid) >> 2, (tid + 256) >> 2 };
    const int ac4     = tid & 3;
    const int brow[2] = { (tid) >> 4, (tid + 256) >> 4 };
    const int bc8     = tid & 15;

    for (int r = tid; r < 128; r += 256) {
        const float bv = bout[m0 + r];
#pragma unroll
        for (int c = 0; c < 16; ++c) brep[r * 16 + c] = bv;
    }
    __syncthreads();

    wmma::fragment<wmma::accumulator, 16, 16, 16, float> acc[4][2];
#pragma unroll
    for (int mi = 0; mi < 4; ++mi)
#pragma unroll
        for (int ni = 0; ni < 2; ++ni)
            wmma::load_matrix_sync(acc[mi][ni],
                                   &brep[(wm * 64 + mi * 16) * 16], 16,
                                   wmma::mem_row_major);

    uint4 rAh[2], rAl[2], rBh[2], rBl[2];
    // prologue: chunk 0
#pragma unroll
    for (int it = 0; it < 2; ++it) {
        const size_t ga = (size_t)(m0 + arow[it]) * 256 + ac4 * 8;
        rAh[it] = *reinterpret_cast<const uint4*>(Ah + ga);
        rAl[it] = *reinterpret_cast<const uint4*>(Al + ga);
        const size_t gb = (size_t)brow[it] * NSEQ + p0 + bc8 * 8;
        rBh[it] = *reinterpret_cast<const uint4*>(Xh + gb);
        rBl[it] = *reinterpret_cast<const uint4*>(Xl + gb);
    }

#pragma unroll 1
    for (int kk = 0; kk < 256; kk += 32) {
        __syncthreads();
#pragma unroll
        for (int it = 0; it < 2; ++it) {
            const int soA = arow[it] * SMS2 + ac4 * 8;
            *reinterpret_cast<uint4*>(&sAh[soA]) = rAh[it];
            *reinterpret_cast<uint4*>(&sAl[soA]) = rAl[it];
            const int soB = brow[it] * OVS + bc8 * 8;
            *reinterpret_cast<uint4*>(&sBh[soB]) = rBh[it];
            *reinterpret_cast<uint4*>(&sBl[soB]) = rBl[it];
        }
        __syncthreads();

        if (kk + 32 < 256) {
#pragma unroll
            for (int it = 0; it < 2; ++it) {
                const size_t ga = (size_t)(m0 + arow[it]) * 256 + kk + 32 + ac4 * 8;
                rAh[it] = *reinterpret_cast<const uint4*>(Ah + ga);
                rAl[it] = *reinterpret_cast<const uint4*>(Al + ga);
                const size_t gb = (size_t)(kk + 32 + brow[it]) * NSEQ + p0 + bc8 * 8;
                rBh[it] = *reinterpret_cast<const uint4*>(Xh + gb);
                rBl[it] = *reinterpret_cast<const uint4*>(Xl + gb);
            }
        }

#pragma unroll
        for (int k2 = 0; k2 < 2; ++k2) {
            wmma::fragment<wmma::matrix_a, 16, 16, 16, __half, wmma::row_major> fah[4], fal[4];
            wmma::fragment<wmma::matrix_b, 16, 16, 16, __half, wmma::row_major> fbh[2], fbl[2];
#pragma unroll
            for (int mi = 0; mi < 4; ++mi) {
                const int ro = (wm * 64 + mi * 16) * SMS2 + k2 * 16;
                wmma::load_matrix_sync(fah[mi], &sAh[ro], SMS2);
                wmma::load_matrix_sync(fal[mi], &sAl[ro], SMS2);
            }
#pragma unroll
            for (int ni = 0; ni < 2; ++ni) {
                const int co = (k2 * 16) * OVS + wn * 32 + ni * 16;
                wmma::load_matrix_sync(fbh[ni], &sBh[co], OVS);
                wmma::load_matrix_sync(fbl[ni], &sBl[co], OVS);
            }
#pragma unroll
            for (int mi = 0; mi < 4; ++mi)
#pragma unroll
                for (int ni = 0; ni < 2; ++ni) {
                    wmma::mma_sync(acc[mi][ni], fah[mi], fbh[ni], acc[mi][ni]);
                    wmma::mma_sync(acc[mi][ni], fah[mi], fbl[ni], acc[mi][ni]);
                    wmma::mma_sync(acc[mi][ni], fal[mi], fbh[ni], acc[mi][ni]);
                }
        }
    }

    float* C = out + (size_t)g * 256 * NSEQ;
#pragma unroll
    for (int mi = 0; mi < 4; ++mi)
#pragma unroll
        for (int ni = 0; ni < 2; ++ni)
            wmma::store_matrix_sync(
                C + (size_t)(m0 + wm * 64 + mi * 16) * NSEQ + p0 + wn * 32 + ni * 16,
                acc[mi][ni], NSEQ, wmma::mem_row_major);
}

// ---------------------------------------------------------------------------
extern "C" void kernel_launch(void* const* d_in, const int* in_sizes, int n_in,
                              void* d_out, int out_size)
{
    const float* x    = (const float*)d_in[0];
    const float* Wq   = (const float*)d_in[1];
    const float* Wkv  = (const float*)d_in[2];
    const float* Wout = (const float*)d_in[3];
    const float* bout = (const float*)d_in[4];
    float* out = (float*)d_out;
    (void)in_sizes; (void)n_in; (void)out_size;

    convert_x   <<<dim3(256, 2), 256>>>(x);
    gram_kernel <<<dim3(GSP, 3, 2), 256>>>();
    gram_reduce <<<dim3(256, 2), 256>>>();
    sq_kernel   <<<dim3(256, 2), 256>>>(Wq);
    simp_kernel <<<dim3(4, 16), 256>>>(Wkv);
    softmax_kernel<<<dim3(64, 16), 64>>>();
    u_kernel    <<<dim3(4, 16), 256>>>(Wkv);
    w2_kernel   <<<dim3(128, 2), 256>>>(Wout);
    final_kernel<<<dim3(NSEQ / 128, 2, 2), 256>>>(bout, out);
}

// round 14
// speedup vs baseline: 1.3610x; 1.1080x over previous
#include <cuda_runtime.h>
#include <cuda_fp16.h>
#include <mma.h>
#include <cstdint>
#include <cstddef>

using namespace nvcuda;

// x: [16][32][128][128] fp32 == X[2][256][16384] (g, f, p)
// Wq: [512][256], Wkv: [1024][256] (K rows 0..511, V rows 512..1023),
// Wout: [256][512], bout: [256], out: [2][256][16384] fp32
//
//   Xh/Xl = split(X)                     (convert_x)
//   G_g = X_g X_g^T  (symmetric)         (gram_kernel + gram_reduce)
//   Sq_g = Wq @ G_g                      (sq_kernel, staged chunks)
//   simp = Sq[h] @ Wk[h]^T (k-split)     (simp_kernel)
//   attn = softmax(0.125 * sum simp)     (softmax_kernel)
//   U_g[h] = attn @ Wv[h]                (u_kernel)
//   W2_g = Wout @ U_g -> fp16 hi/lo      (w2_kernel, staged chunks)
//   out_g = W2_g @ X_g + bout            (final_kernel)

#define NSEQ 16384
#define SMS2 40    // fp16 staging stride, 32-half rows (+pad)
#define OVS  136   // fp16 staging stride, 128-half rows (+pad)
#define GSP  32    // gram k-splits
#define FAS  68    // fp32 staging stride (floats), 64-wide tiles

// ------------------------------ scratch ------------------------------------
__device__ __half g_xh  [(size_t)2 * 256 * 16384];      // X hi
__device__ __half g_xl  [(size_t)2 * 256 * 16384];      // X lo
__device__ float  g_gpart[(size_t)2 * GSP * 256 * 256]; // gram partials
__device__ float  g_gram [(size_t)2 * 256 * 256];
__device__ float  g_sq   [(size_t)2 * 512 * 256];
__device__ float  g_simp [(size_t)16 * 4 * 64 * 64];    // sim k-split partials
__device__ float  g_attn [(size_t)16 * 64 * 64];
__device__ float  g_u    [(size_t)2 * 512 * 256];
__device__ __half g_w2_h [(size_t)2 * 256 * 256];
__device__ __half g_w2_l [(size_t)2 * 256 * 256];

__device__ __forceinline__ void split_hl(float v, __half& hi, __half& lo) {
    hi = __float2half_rn(v);
    lo = __float2half_rn(v - __half2float(hi));
}

// ---------------------------------------------------------------------------
// Kernel 0: X fp32 -> Xh/Xl fp16 (same [g][f][p] layout)
// ---------------------------------------------------------------------------
__global__ void __launch_bounds__(256) convert_x(const float* __restrict__ x)
{
    const size_t base = ((size_t)blockIdx.y * 256 + blockIdx.x) * NSEQ;
    const float4* src = reinterpret_cast<const float4*>(x + base);
    uint4* dh = reinterpret_cast<uint4*>(g_xh + base);
    uint4* dl = reinterpret_cast<uint4*>(g_xl + base);
    for (int t = threadIdx.x; t < 2048; t += 256) {
        const float4 v0 = src[2 * t], v1 = src[2 * t + 1];
        __half h[8], l[8];
        split_hl(v0.x, h[0], l[0]); split_hl(v0.y, h[1], l[1]);
        split_hl(v0.z, h[2], l[2]); split_hl(v0.w, h[3], l[3]);
        split_hl(v1.x, h[4], l[4]); split_hl(v1.y, h[5], l[5]);
        split_hl(v1.z, h[6], l[6]); split_hl(v1.w, h[7], l[7]);
        dh[t] = *reinterpret_cast<uint4*>(h);
        dl[t] = *reinterpret_cast<uint4*>(l);
    }
}

// ---------------------------------------------------------------------------
// Kernel 1: gram partials (symmetric), register-prefetch double buffered.
// ---------------------------------------------------------------------------
__global__ void __launch_bounds__(256) gram_kernel()
{
    __shared__ __align__(32) __half sAh[128 * SMS2];
    __shared__ __align__(32) __half sAl[128 * SMS2];
    __shared__ __align__(32) __half sBh[128 * SMS2];
    __shared__ __align__(32) __half sBl[128 * SMS2];

    const int ks = blockIdx.x;
    const int y  = blockIdx.y;
    const int g  = blockIdx.z;
    const int tm = (y >= 1), tn = (y == 2);
    const bool diag = (tm == tn);
    const int p0 = ks * 512;

    const __half* Xh = g_xh + (size_t)g * 256 * NSEQ;
    const __half* Xl = g_xl + (size_t)g * 256 * NSEQ;

    const int tid = threadIdx.x;
    const int wid = tid >> 5;
    const int wm = wid >> 2, wn = wid & 3;
    const int lc4  = tid & 3;
    const int rows[2] = { (tid) >> 2, (tid + 256) >> 2 };

    wmma::fragment<wmma::accumulator, 16, 16, 16, float> acc[4][2];
#pragma unroll
    for (int mi = 0; mi < 4; ++mi)
#pragma unroll
        for (int ni = 0; ni < 2; ++ni) wmma::fill_fragment(acc[mi][ni], 0.0f);

    const __half* pBh = diag ? sAh : sBh;
    const __half* pBl = diag ? sAl : sBl;

    uint4 rAh[2], rAl[2], rBh[2], rBl[2];

#pragma unroll
    for (int it = 0; it < 2; ++it) {
        const size_t ga = (size_t)(tm * 128 + rows[it]) * NSEQ + p0 + lc4 * 8;
        rAh[it] = *reinterpret_cast<const uint4*>(Xh + ga);
        rAl[it] = *reinterpret_cast<const uint4*>(Xl + ga);
        if (!diag) {
            const size_t gb = (size_t)(tn * 128 + rows[it]) * NSEQ + p0 + lc4 * 8;
            rBh[it] = *reinterpret_cast<const uint4*>(Xh + gb);
            rBl[it] = *reinterpret_cast<const uint4*>(Xl + gb);
        }
    }

#pragma unroll 1
    for (int pc = 0; pc < 512; pc += 32) {
        __syncthreads();
#pragma unroll
        for (int it = 0; it < 2; ++it) {
            const int so = rows[it] * SMS2 + lc4 * 8;
            *reinterpret_cast<uint4*>(&sAh[so]) = rAh[it];
            *reinterpret_cast<uint4*>(&sAl[so]) = rAl[it];
            if (!diag) {
                *reinterpret_cast<uint4*>(&sBh[so]) = rBh[it];
                *reinterpret_cast<uint4*>(&sBl[so]) = rBl[it];
            }
        }
        __syncthreads();

        if (pc + 32 < 512) {
#pragma unroll
            for (int it = 0; it < 2; ++it) {
                const size_t ga = (size_t)(tm * 128 + rows[it]) * NSEQ
                                + p0 + pc + 32 + lc4 * 8;
                rAh[it] = *reinterpret_cast<const uint4*>(Xh + ga);
                rAl[it] = *reinterpret_cast<const uint4*>(Xl + ga);
                if (!diag) {
                    const size_t gb = (size_t)(tn * 128 + rows[it]) * NSEQ
                                    + p0 + pc + 32 + lc4 * 8;
                    rBh[it] = *reinterpret_cast<const uint4*>(Xh + gb);
                    rBl[it] = *reinterpret_cast<const uint4*>(Xl + gb);
                }
            }
        }

#pragma unroll
        for (int k2 = 0; k2 < 2; ++k2) {
            wmma::fragment<wmma::matrix_a, 16, 16, 16, __half, wmma::row_major> fah[4], fal[4];
            wmma::fragment<wmma::matrix_b, 16, 16, 16, __half, wmma::col_major> fbh[2], fbl[2];
#pragma unroll
            for (int mi = 0; mi < 4; ++mi) {
                const int ro = (wm * 64 + mi * 16) * SMS2 + k2 * 16;
                wmma::load_matrix_sync(fah[mi], &sAh[ro], SMS2);
                wmma::load_matrix_sync(fal[mi], &sAl[ro], SMS2);
            }
#pragma unroll
            for (int ni = 0; ni < 2; ++ni) {
                const int ro = (wn * 32 + ni * 16) * SMS2 + k2 * 16;
                wmma::load_matrix_sync(fbh[ni], &pBh[ro], SMS2);
                wmma::load_matrix_sync(fbl[ni], &pBl[ro], SMS2);
            }
#pragma unroll
            for (int mi = 0; mi < 4; ++mi)
#pragma unroll
                for (int ni = 0; ni < 2; ++ni) {
                    wmma::mma_sync(acc[mi][ni], fah[mi], fbh[ni], acc[mi][ni]);
                    wmma::mma_sync(acc[mi][ni], fah[mi], fbl[ni], acc[mi][ni]);
                    wmma::mma_sync(acc[mi][ni], fal[mi], fbh[ni], acc[mi][ni]);
                }
        }
    }

    float* P = g_gpart + (size_t)(g * GSP + ks) * 65536;
#pragma unroll
    for (int mi = 0; mi < 4; ++mi)
#pragma unroll
        for (int ni = 0; ni < 2; ++ni) {
            const int rb = tm * 128 + wm * 64 + mi * 16;
            const int cb = tn * 128 + wn * 32 + ni * 16;
            wmma::store_matrix_sync(P + (size_t)rb * 256 + cb, acc[mi][ni],
                                    256, wmma::mem_row_major);
            if (tm != tn)
                wmma::store_matrix_sync(P + (size_t)cb * 256 + rb, acc[mi][ni],
                                        256, wmma::mem_col_major);
        }
}

// ---------------------------------------------------------------------------
// Kernel 2: reduce gram partials.
// ---------------------------------------------------------------------------
__global__ void __launch_bounds__(256) gram_reduce()
{
    const int a = blockIdx.x, g = blockIdx.y, b = threadIdx.x;
    float s = 0.f;
#pragma unroll 8
    for (int ks = 0; ks < GSP; ++ks)
        s += g_gpart[((size_t)(g * GSP + ks) * 256 + a) * 256 + b];
    g_gram[((size_t)g * 256 + a) * 256 + b] = s;
}

// ---------------------------------------------------------------------------
// Kernel 3: Sq_g = Wq @ G_g  (512x256 per group, K=256, fp32)
// 4-row tiles, G staged in SMEM chunks of 32 rows (coalesced, MLP=8).
// grid (128, 2).
// ---------------------------------------------------------------------------
__global__ void __launch_bounds__(256) sq_kernel(const float* __restrict__ Wq)
{
    __shared__ float s_w[4 * 256];
    __shared__ __align__(16) float s_g[32 * 256];

    const int m0 = blockIdx.x * 4, g = blockIdx.y, n = threadIdx.x;
    const float* G = g_gram + (size_t)g * 65536;

#pragma unroll
    for (int r = 0; r < 4; ++r)
        s_w[r * 256 + n] = Wq[(size_t)(m0 + r) * 256 + n];

    float acc[4] = {};
#pragma unroll 1
    for (int kc = 0; kc < 256; kc += 32) {
        __syncthreads();
        const float4* Gv = reinterpret_cast<const float4*>(G + (size_t)kc * 256);
        float4* sg4 = reinterpret_cast<float4*>(s_g);
#pragma unroll
        for (int it = 0; it < 8; ++it)
            sg4[n + it * 256] = Gv[n + it * 256];
        __syncthreads();
#pragma unroll
        for (int k = 0; k < 32; ++k) {
            const float gv = s_g[k * 256 + n];
#pragma unroll
            for (int r = 0; r < 4; ++r)
                acc[r] = fmaf(s_w[r * 256 + kc + k], gv, acc[r]);
        }
    }
#pragma unroll
    for (int r = 0; r < 4; ++r)
        g_sq[((size_t)g * 512 + m0 + r) * 256 + n] = acc[r];
}

// ---------------------------------------------------------------------------
// Kernel 4: sim partials. grid (4 ksplit, 16 gh). 64x64 out, K=64 per block.
// ---------------------------------------------------------------------------
__global__ void __launch_bounds__(256) simp_kernel(const float* __restrict__ Wkv)
{
    __shared__ __align__(16) float s_q[64 * FAS];
    __shared__ __align__(16) float s_k[64 * FAS];

    const int ks = blockIdx.x, gh = blockIdx.y;
    const int g = gh >> 3, h = gh & 7;
    const int tid = threadIdx.x;

    const float* SQ = g_sq + ((size_t)g * 512 + h * 64) * 256 + ks * 64;
    const float* WK = Wkv + (size_t)(h * 64) * 256 + ks * 64;

#pragma unroll
    for (int it = 0; it < 4; ++it) {
        const int idx = tid + it * 256;
        const int row = idx >> 4, c4 = idx & 15;
        *reinterpret_cast<float4*>(&s_q[row * FAS + c4 * 4]) =
            *reinterpret_cast<const float4*>(SQ + (size_t)row * 256 + c4 * 4);
        *reinterpret_cast<float4*>(&s_k[row * FAS + c4 * 4]) =
            *reinterpret_cast<const float4*>(WK + (size_t)row * 256 + c4 * 4);
    }
    __syncthreads();

    const int i0 = (tid >> 4) * 4, j0 = (tid & 15) * 4;
    float acc[4][4] = {};
#pragma unroll
    for (int k = 0; k < 64; k += 4) {
        float4 qv[4], kv[4];
#pragma unroll
        for (int a = 0; a < 4; ++a) {
            qv[a] = *reinterpret_cast<const float4*>(&s_q[(i0 + a) * FAS + k]);
            kv[a] = *reinterpret_cast<const float4*>(&s_k[(j0 + a) * FAS + k]);
        }
#pragma unroll
        for (int a = 0; a < 4; ++a)
#pragma unroll
            for (int b = 0; b < 4; ++b)
                acc[a][b] += qv[a].x * kv[b].x + qv[a].y * kv[b].y
                           + qv[a].z * kv[b].z + qv[a].w * kv[b].w;
    }

    float* P = g_simp + (size_t)(gh * 4 + ks) * 4096;
#pragma unroll
    for (int a = 0; a < 4; ++a)
        *reinterpret_cast<float4*>(&P[(i0 + a) * 64 + j0]) =
            make_float4(acc[a][0], acc[a][1], acc[a][2], acc[a][3]);
}

// ---------------------------------------------------------------------------
// Kernel 5: reduce sim partials + scale + softmax. grid (64, 16), 64 thr.
// ---------------------------------------------------------------------------
__global__ void __launch_bounds__(64) softmax_kernel()
{
    const int i  = blockIdx.x;
    const int gh = blockIdx.y;
    const int j  = threadIdx.x;

    float v = 0.f;
#pragma unroll
    for (int ks = 0; ks < 4; ++ks)
        v += g_simp[(size_t)(gh * 4 + ks) * 4096 + i * 64 + j];
    v *= 0.125f;

    __shared__ float s[64];
    __shared__ float red;
    s[j] = v;
    __syncthreads();
    if (j == 0) {
        float m = s[0];
        for (int t = 1; t < 64; ++t) m = fmaxf(m, s[t]);
        red = m;
    }
    __syncthreads();
    const float e = __expf(v - red);
    s[j] = e;
    __syncthreads();
    if (j == 0) {
        float su = 0.f;
        for (int t = 0; t < 64; ++t) su += s[t];
        red = su;
    }
    __syncthreads();
    g_attn[(size_t)gh * 4096 + i * 64 + j] = e / red;
}

// ---------------------------------------------------------------------------
// Kernel 6: U = attn @ Wv. grid (4 ftile, 16 gh). 64x64 out, K=64.
// ---------------------------------------------------------------------------
__global__ void __launch_bounds__(256) u_kernel(const float* __restrict__ Wkv)
{
    __shared__ __align__(16) float s_a[64 * FAS];
    __shared__ __align__(16) float s_w[64 * FAS];

    const int ft = blockIdx.x, gh = blockIdx.y;
    const int g = gh >> 3, h = gh & 7;
    const int tid = threadIdx.x;

    const float* A  = g_attn + (size_t)gh * 4096;
    const float* WV = Wkv + (size_t)(512 + h * 64) * 256 + ft * 64;

#pragma unroll
    for (int it = 0; it < 4; ++it) {
        const int idx = tid + it * 256;
        const int row = idx >> 4, c4 = idx & 15;
        *reinterpret_cast<float4*>(&s_a[row * FAS + c4 * 4]) =
            *reinterpret_cast<const float4*>(A + (size_t)row * 64 + c4 * 4);
        *reinterpret_cast<float4*>(&s_w[row * FAS + c4 * 4]) =
            *reinterpret_cast<const float4*>(WV + (size_t)row * 256 + c4 * 4);
    }
    __syncthreads();

    const int i0 = (tid >> 4) * 4, f0 = (tid & 15) * 4;
    float acc[4][4] = {};
#pragma unroll
    for (int j = 0; j < 64; ++j) {
        const float4 wv = *reinterpret_cast<const float4*>(&s_w[j * FAS + f0]);
        float av[4];
#pragma unroll
        for (int a = 0; a < 4; ++a) av[a] = s_a[(i0 + a) * FAS + j];
#pragma unroll
        for (int a = 0; a < 4; ++a) {
            acc[a][0] += av[a] * wv.x; acc[a][1] += av[a] * wv.y;
            acc[a][2] += av[a] * wv.z; acc[a][3] += av[a] * wv.w;
        }
    }

    float* U = g_u + ((size_t)g * 512 + h * 64) * 256 + ft * 64;
#pragma unroll
    for (int a = 0; a < 4; ++a)
        *reinterpret_cast<float4*>(&U[(size_t)(i0 + a) * 256 + f0]) =
            make_float4(acc[a][0], acc[a][1], acc[a][2], acc[a][3]);
}

// ---------------------------------------------------------------------------
// Kernel 7: W2_g = Wout @ U_g -> fp16 hi/lo (256x256 per group, K=512)
// 4-row tiles, U staged in SMEM chunks of 32 rows. grid (64, 2).
// ---------------------------------------------------------------------------
__global__ void __launch_bounds__(256) w2_kernel(const float* __restrict__ Wout)
{
    __shared__ float s_w[4 * 512];
    __shared__ __align__(16) float s_u[32 * 256];

    const int m0 = blockIdx.x * 4, g = blockIdx.y, n = threadIdx.x;
    const float* Ug = g_u + (size_t)g * 512 * 256;

#pragma unroll
    for (int r = 0; r < 4; ++r) {
        s_w[r * 512 + n]       = Wout[(size_t)(m0 + r) * 512 + n];
        s_w[r * 512 + 256 + n] = Wout[(size_t)(m0 + r) * 512 + 256 + n];
    }

    float acc[4] = {};
#pragma unroll 1
    for (int cc = 0; cc < 512; cc += 32) {
        __syncthreads();
        const float4* Uv = reinterpret_cast<const float4*>(Ug + (size_t)cc * 256);
        float4* su4 = reinterpret_cast<float4*>(s_u);
#pragma unroll
        for (int it = 0; it < 8; ++it)
            su4[n + it * 256] = Uv[n + it * 256];
        __syncthreads();
#pragma unroll
        for (int k = 0; k < 32; ++k) {
            const float uv = s_u[k * 256 + n];
#pragma unroll
            for (int r = 0; r < 4; ++r)
                acc[r] = fmaf(s_w[r * 512 + cc + k], uv, acc[r]);
        }
    }
#pragma unroll
    for (int r = 0; r < 4; ++r) {
        __half hv, lv;
        split_hl(acc[r], hv, lv);
        g_w2_h[((size_t)g * 256 + m0 + r) * 256 + n] = hv;
        g_w2_l[((size_t)g * 256 + m0 + r) * 256 + n] = lv;
    }
}

// ---------------------------------------------------------------------------
// Kernel 8: out_g = W2_g @ X_g + bout.  M=256, N=16384, K=256.
// Register-prefetch double buffered.
// ---------------------------------------------------------------------------
__global__ void __launch_bounds__(256) final_kernel(const float* __restrict__ bout,
                                                    float* __restrict__ out)
{
    __shared__ __align__(32) __half sAh[128 * SMS2];
    __shared__ __align__(32) __half sAl[128 * SMS2];
    __shared__ __align__(32) __half sBh[32 * OVS];
    __shared__ __align__(32) __half sBl[32 * OVS];
    __shared__ __align__(32) float  brep[128 * 16];

    const int tid = threadIdx.x;
    const int wid = tid >> 5;
    const int wm = wid >> 2, wn = wid & 3;
    const int p0 = blockIdx.x * 128;
    const int m0 = blockIdx.y * 128;
    const int g  = blockIdx.z;

    const __half* Ah = g_w2_h + (size_t)g * 65536;
    const __half* Al = g_w2_l + (size_t)g * 65536;
    const __half* Xh = g_xh + (size_t)g * 256 * NSEQ;
    const __half* Xl = g_xl + (size_t)g * 256 * NSEQ;

    const int arow[2] = { (tid) >> 2, (tid + 256) >> 2 };
    const int ac4     = tid & 3;
    const int brow[2] = { (tid) >> 4, (tid + 256) >> 4 };
    const int bc8     = tid & 15;

    for (int r = tid; r < 128; r += 256) {
        const float bv = bout[m0 + r];
#pragma unroll
        for (int c = 0; c < 16; ++c) brep[r * 16 + c] = bv;
    }
    __syncthreads();

    wmma::fragment<wmma::accumulator, 16, 16, 16, float> acc[4][2];
#pragma unroll
    for (int mi = 0; mi < 4; ++mi)
#pragma unroll
        for (int ni = 0; ni < 2; ++ni)
            wmma::load_matrix_sync(acc[mi][ni],
                                   &brep[(wm * 64 + mi * 16) * 16], 16,
                                   wmma::mem_row_major);

    uint4 rAh[2], rAl[2], rBh[2], rBl[2];
#pragma unroll
    for (int it = 0; it < 2; ++it) {
        const size_t ga = (size_t)(m0 + arow[it]) * 256 + ac4 * 8;
        rAh[it] = *reinterpret_cast<const uint4*>(Ah + ga);
        rAl[it] = *reinterpret_cast<const uint4*>(Al + ga);
        const size_t gb = (size_t)brow[it] * NSEQ + p0 + bc8 * 8;
        rBh[it] = *reinterpret_cast<const uint4*>(Xh + gb);
        rBl[it] = *reinterpret_cast<const uint4*>(Xl + gb);
    }

#pragma unroll 1
    for (int kk = 0; kk < 256; kk += 32) {
        __syncthreads();
#pragma unroll
        for (int it = 0; it < 2; ++it) {
            const int soA = arow[it] * SMS2 + ac4 * 8;
            *reinterpret_cast<uint4*>(&sAh[soA]) = rAh[it];
            *reinterpret_cast<uint4*>(&sAl[soA]) = rAl[it];
            const int soB = brow[it] * OVS + bc8 * 8;
            *reinterpret_cast<uint4*>(&sBh[soB]) = rBh[it];
            *reinterpret_cast<uint4*>(&sBl[soB]) = rBl[it];
        }
        __syncthreads();

        if (kk + 32 < 256) {
#pragma unroll
            for (int it = 0; it < 2; ++it) {
                const size_t ga = (size_t)(m0 + arow[it]) * 256 + kk + 32 + ac4 * 8;
                rAh[it] = *reinterpret_cast<const uint4*>(Ah + ga);
                rAl[it] = *reinterpret_cast<const uint4*>(Al + ga);
                const size_t gb = (size_t)(kk + 32 + brow[it]) * NSEQ + p0 + bc8 * 8;
                rBh[it] = *reinterpret_cast<const uint4*>(Xh + gb);
                rBl[it] = *reinterpret_cast<const uint4*>(Xl + gb);
            }
        }

#pragma unroll
        for (int k2 = 0; k2 < 2; ++k2) {
            wmma::fragment<wmma::matrix_a, 16, 16, 16, __half, wmma::row_major> fah[4], fal[4];
            wmma::fragment<wmma::matrix_b, 16, 16, 16, __half, wmma::row_major> fbh[2], fbl[2];
#pragma unroll
            for (int mi = 0; mi < 4; ++mi) {
                const int ro = (wm * 64 + mi * 16) * SMS2 + k2 * 16;
                wmma::load_matrix_sync(fah[mi], &sAh[ro], SMS2);
                wmma::load_matrix_sync(fal[mi], &sAl[ro], SMS2);
            }
#pragma unroll
            for (int ni = 0; ni < 2; ++ni) {
                const int co = (k2 * 16) * OVS + wn * 32 + ni * 16;
                wmma::load_matrix_sync(fbh[ni], &sBh[co], OVS);
                wmma::load_matrix_sync(fbl[ni], &sBl[co], OVS);
            }
#pragma unroll
            for (int mi = 0; mi < 4; ++mi)
#pragma unroll
                for (int ni = 0; ni < 2; ++ni) {
                    wmma::mma_sync(acc[mi][ni], fah[mi], fbh[ni], acc[mi][ni]);
                    wmma::mma_sync(acc[mi][ni], fah[mi], fbl[ni], acc[mi][ni]);
                    wmma::mma_sync(acc[mi][ni], fal[mi], fbh[ni], acc[mi][ni]);
                }
        }
    }

    float* C = out + (size_t)g * 256 * NSEQ;
#pragma unroll
    for (int mi = 0; mi < 4; ++mi)
#pragma unroll
        for (int ni = 0; ni < 2; ++ni)
            wmma::store_matrix_sync(
                C + (size_t)(m0 + wm * 64 + mi * 16) * NSEQ + p0 + wn * 32 + ni * 16,
                acc[mi][ni], NSEQ, wmma::mem_row_major);
}

// ---------------------------------------------------------------------------
extern "C" void kernel_launch(void* const* d_in, const int* in_sizes, int n_in,
                              void* d_out, int out_size)
{
    const float* x    = (const float*)d_in[0];
    const float* Wq   = (const float*)d_in[1];
    const float* Wkv  = (const float*)d_in[2];
    const float* Wout = (const float*)d_in[3];
    const float* bout = (const float*)d_in[4];
    float* out = (float*)d_out;
    (void)in_sizes; (void)n_in; (void)out_size;

    convert_x   <<<dim3(256, 2), 256>>>(x);
    gram_kernel <<<dim3(GSP, 3, 2), 256>>>();
    gram_reduce <<<dim3(256, 2), 256>>>();
    sq_kernel   <<<dim3(128, 2), 256>>>(Wq);
    simp_kernel <<<dim3(4, 16), 256>>>(Wkv);
    softmax_kernel<<<dim3(64, 16), 64>>>();
    u_kernel    <<<dim3(4, 16), 256>>>(Wkv);
    w2_kernel   <<<dim3(64, 2), 256>>>(Wout);
    final_kernel<<<dim3(NSEQ / 128, 2, 2), 256>>>(bout, out);
}

// round 15
// speedup vs baseline: 1.4026x; 1.0306x over previous
#include <cuda_runtime.h>
#include <cuda_fp16.h>
#include <mma.h>
#include <cstdint>
#include <cstddef>

using namespace nvcuda;

// x: [16][32][128][128] fp32 == X[2][256][16384] (g, f, p)
// Wq: [512][256], Wkv: [1024][256] (K rows 0..511, V rows 512..1023),
// Wout: [256][512], bout: [256], out: [2][256][16384] fp32
//
//   Xh/Xl = split(X)                     (convert_x)
//   G_g = X_g X_g^T  (symmetric, 3-term) (gram_kernel + gram_reduce)
//   Sq_g = Wq @ G_g                      (sq_kernel, prefetch-staged)
//   simp = Sq[h] @ Wk[h]^T (k-split)     (simp_kernel)
//   attn = softmax(0.125 * sum simp)     (softmax_kernel)
//   U_g[h] = attn @ Wv[h]                (u_kernel)
//   W2_g = Wout @ U_g -> fp16 hi/lo      (w2_kernel, prefetch-staged)
//   out_g = W2 @ Xhi + bout  (2-term)    (final_kernel)

#define NSEQ 16384
#define SMS2 40    // fp16 staging stride, 32-half rows (+pad)
#define OVS  136   // fp16 staging stride, 128-half rows (+pad)
#define GSP  32    // gram k-splits
#define FAS  68    // fp32 staging stride (floats), 64-wide tiles

// ------------------------------ scratch ------------------------------------
__device__ __half g_xh  [(size_t)2 * 256 * 16384];      // X hi
__device__ __half g_xl  [(size_t)2 * 256 * 16384];      // X lo
__device__ float  g_gpart[(size_t)2 * GSP * 256 * 256]; // gram partials
__device__ float  g_gram [(size_t)2 * 256 * 256];
__device__ float  g_sq   [(size_t)2 * 512 * 256];
__device__ float  g_simp [(size_t)16 * 4 * 64 * 64];    // sim k-split partials
__device__ float  g_attn [(size_t)16 * 64 * 64];
__device__ float  g_u    [(size_t)2 * 512 * 256];
__device__ __half g_w2_h [(size_t)2 * 256 * 256];
__device__ __half g_w2_l [(size_t)2 * 256 * 256];

__device__ __forceinline__ void split_hl(float v, __half& hi, __half& lo) {
    hi = __float2half_rn(v);
    lo = __float2half_rn(v - __half2float(hi));
}

// ---------------------------------------------------------------------------
// Kernel 0: X fp32 -> Xh/Xl fp16 (same [g][f][p] layout)
// ---------------------------------------------------------------------------
__global__ void __launch_bounds__(256) convert_x(const float* __restrict__ x)
{
    const size_t base = ((size_t)blockIdx.y * 256 + blockIdx.x) * NSEQ;
    const float4* src = reinterpret_cast<const float4*>(x + base);
    uint4* dh = reinterpret_cast<uint4*>(g_xh + base);
    uint4* dl = reinterpret_cast<uint4*>(g_xl + base);
    for (int t = threadIdx.x; t < 2048; t += 256) {
        const float4 v0 = src[2 * t], v1 = src[2 * t + 1];
        __half h[8], l[8];
        split_hl(v0.x, h[0], l[0]); split_hl(v0.y, h[1], l[1]);
        split_hl(v0.z, h[2], l[2]); split_hl(v0.w, h[3], l[3]);
        split_hl(v1.x, h[4], l[4]); split_hl(v1.y, h[5], l[5]);
        split_hl(v1.z, h[6], l[6]); split_hl(v1.w, h[7], l[7]);
        dh[t] = *reinterpret_cast<uint4*>(h);
        dl[t] = *reinterpret_cast<uint4*>(l);
    }
}

// ---------------------------------------------------------------------------
// Kernel 1: gram partials (symmetric, 3-term), register-prefetch buffered.
// ---------------------------------------------------------------------------
__global__ void __launch_bounds__(256) gram_kernel()
{
    __shared__ __align__(32) __half sAh[128 * SMS2];
    __shared__ __align__(32) __half sAl[128 * SMS2];
    __shared__ __align__(32) __half sBh[128 * SMS2];
    __shared__ __align__(32) __half sBl[128 * SMS2];

    const int ks = blockIdx.x;
    const int y  = blockIdx.y;
    const int g  = blockIdx.z;
    const int tm = (y >= 1), tn = (y == 2);
    const bool diag = (tm == tn);
    const int p0 = ks * 512;

    const __half* Xh = g_xh + (size_t)g * 256 * NSEQ;
    const __half* Xl = g_xl + (size_t)g * 256 * NSEQ;

    const int tid = threadIdx.x;
    const int wid = tid >> 5;
    const int wm = wid >> 2, wn = wid & 3;
    const int lc4  = tid & 3;
    const int rows[2] = { (tid) >> 2, (tid + 256) >> 2 };

    wmma::fragment<wmma::accumulator, 16, 16, 16, float> acc[4][2];
#pragma unroll
    for (int mi = 0; mi < 4; ++mi)
#pragma unroll
        for (int ni = 0; ni < 2; ++ni) wmma::fill_fragment(acc[mi][ni], 0.0f);

    const __half* pBh = diag ? sAh : sBh;
    const __half* pBl = diag ? sAl : sBl;

    uint4 rAh[2], rAl[2], rBh[2], rBl[2];

#pragma unroll
    for (int it = 0; it < 2; ++it) {
        const size_t ga = (size_t)(tm * 128 + rows[it]) * NSEQ + p0 + lc4 * 8;
        rAh[it] = *reinterpret_cast<const uint4*>(Xh + ga);
        rAl[it] = *reinterpret_cast<const uint4*>(Xl + ga);
        if (!diag) {
            const size_t gb = (size_t)(tn * 128 + rows[it]) * NSEQ + p0 + lc4 * 8;
            rBh[it] = *reinterpret_cast<const uint4*>(Xh + gb);
            rBl[it] = *reinterpret_cast<const uint4*>(Xl + gb);
        }
    }

#pragma unroll 1
    for (int pc = 0; pc < 512; pc += 32) {
        __syncthreads();
#pragma unroll
        for (int it = 0; it < 2; ++it) {
            const int so = rows[it] * SMS2 + lc4 * 8;
            *reinterpret_cast<uint4*>(&sAh[so]) = rAh[it];
            *reinterpret_cast<uint4*>(&sAl[so]) = rAl[it];
            if (!diag) {
                *reinterpret_cast<uint4*>(&sBh[so]) = rBh[it];
                *reinterpret_cast<uint4*>(&sBl[so]) = rBl[it];
            }
        }
        __syncthreads();

        if (pc + 32 < 512) {
#pragma unroll
            for (int it = 0; it < 2; ++it) {
                const size_t ga = (size_t)(tm * 128 + rows[it]) * NSEQ
                                + p0 + pc + 32 + lc4 * 8;
                rAh[it] = *reinterpret_cast<const uint4*>(Xh + ga);
                rAl[it] = *reinterpret_cast<const uint4*>(Xl + ga);
                if (!diag) {
                    const size_t gb = (size_t)(tn * 128 + rows[it]) * NSEQ
                                    + p0 + pc + 32 + lc4 * 8;
                    rBh[it] = *reinterpret_cast<const uint4*>(Xh + gb);
                    rBl[it] = *reinterpret_cast<const uint4*>(Xl + gb);
                }
            }
        }

#pragma unroll
        for (int k2 = 0; k2 < 2; ++k2) {
            wmma::fragment<wmma::matrix_a, 16, 16, 16, __half, wmma::row_major> fah[4], fal[4];
            wmma::fragment<wmma::matrix_b, 16, 16, 16, __half, wmma::col_major> fbh[2], fbl[2];
#pragma unroll
            for (int mi = 0; mi < 4; ++mi) {
                const int ro = (wm * 64 + mi * 16) * SMS2 + k2 * 16;
                wmma::load_matrix_sync(fah[mi], &sAh[ro], SMS2);
                wmma::load_matrix_sync(fal[mi], &sAl[ro], SMS2);
            }
#pragma unroll
            for (int ni = 0; ni < 2; ++ni) {
                const int ro = (wn * 32 + ni * 16) * SMS2 + k2 * 16;
                wmma::load_matrix_sync(fbh[ni], &pBh[ro], SMS2);
                wmma::load_matrix_sync(fbl[ni], &pBl[ro], SMS2);
            }
#pragma unroll
            for (int mi = 0; mi < 4; ++mi)
#pragma unroll
                for (int ni = 0; ni < 2; ++ni) {
                    wmma::mma_sync(acc[mi][ni], fah[mi], fbh[ni], acc[mi][ni]);
                    wmma::mma_sync(acc[mi][ni], fah[mi], fbl[ni], acc[mi][ni]);
                    wmma::mma_sync(acc[mi][ni], fal[mi], fbh[ni], acc[mi][ni]);
                }
        }
    }

    float* P = g_gpart + (size_t)(g * GSP + ks) * 65536;
#pragma unroll
    for (int mi = 0; mi < 4; ++mi)
#pragma unroll
        for (int ni = 0; ni < 2; ++ni) {
            const int rb = tm * 128 + wm * 64 + mi * 16;
            const int cb = tn * 128 + wn * 32 + ni * 16;
            wmma::store_matrix_sync(P + (size_t)rb * 256 + cb, acc[mi][ni],
                                    256, wmma::mem_row_major);
            if (tm != tn)
                wmma::store_matrix_sync(P + (size_t)cb * 256 + rb, acc[mi][ni],
                                        256, wmma::mem_col_major);
        }
}

// ---------------------------------------------------------------------------
// Kernel 2: reduce gram partials (float4 vectorized). grid (64, 2).
// ---------------------------------------------------------------------------
__global__ void __launch_bounds__(256) gram_reduce()
{
    const int g = blockIdx.y;
    const int idx = blockIdx.x * 256 + threadIdx.x;   // float4 index 0..16383
    const float4* P = reinterpret_cast<const float4*>(g_gpart) + (size_t)g * GSP * 16384;
    float4 s = make_float4(0.f, 0.f, 0.f, 0.f);
#pragma unroll 8
    for (int ks = 0; ks < GSP; ++ks) {
        const float4 v = P[(size_t)ks * 16384 + idx];
        s.x += v.x; s.y += v.y; s.z += v.z; s.w += v.w;
    }
    reinterpret_cast<float4*>(g_gram)[(size_t)g * 16384 + idx] = s;
}

// ---------------------------------------------------------------------------
// Kernel 3: Sq_g = Wq @ G_g  (512x256 per group, K=256, fp32)
// 4-row tiles, G staged in 32-row chunks with register prefetch. grid (128,2).
// ---------------------------------------------------------------------------
__global__ void __launch_bounds__(256) sq_kernel(const float* __restrict__ Wq)
{
    __shared__ float s_w[4 * 256];
    __shared__ __align__(16) float s_g[32 * 256];

    const int m0 = blockIdx.x * 4, g = blockIdx.y, n = threadIdx.x;
    const float* G = g_gram + (size_t)g * 65536;
    const float4* Gv = reinterpret_cast<const float4*>(G);
    float4* sg4 = reinterpret_cast<float4*>(s_g);

#pragma unroll
    for (int r = 0; r < 4; ++r)
        s_w[r * 256 + n] = Wq[(size_t)(m0 + r) * 256 + n];

    float4 pre[8];
#pragma unroll
    for (int it = 0; it < 8; ++it)
        pre[it] = Gv[n + it * 256];

    float acc[4] = {};
#pragma unroll 1
    for (int kc = 0; kc < 256; kc += 32) {
        __syncthreads();
#pragma unroll
        for (int it = 0; it < 8; ++it)
            sg4[n + it * 256] = pre[it];
        __syncthreads();
        if (kc + 32 < 256) {
            const float4* Gn = Gv + (size_t)(kc + 32) * 64;
#pragma unroll
            for (int it = 0; it < 8; ++it)
                pre[it] = Gn[n + it * 256];
        }
#pragma unroll
        for (int k = 0; k < 32; ++k) {
            const float gv = s_g[k * 256 + n];
#pragma unroll
            for (int r = 0; r < 4; ++r)
                acc[r] = fmaf(s_w[r * 256 + kc + k], gv, acc[r]);
        }
    }
#pragma unroll
    for (int r = 0; r < 4; ++r)
        g_sq[((size_t)g * 512 + m0 + r) * 256 + n] = acc[r];
}

// ---------------------------------------------------------------------------
// Kernel 4: sim partials. grid (4 ksplit, 16 gh). 64x64 out, K=64 per block.
// ---------------------------------------------------------------------------
__global__ void __launch_bounds__(256) simp_kernel(const float* __restrict__ Wkv)
{
    __shared__ __align__(16) float s_q[64 * FAS];
    __shared__ __align__(16) float s_k[64 * FAS];

    const int ks = blockIdx.x, gh = blockIdx.y;
    const int g = gh >> 3, h = gh & 7;
    const int tid = threadIdx.x;

    const float* SQ = g_sq + ((size_t)g * 512 + h * 64) * 256 + ks * 64;
    const float* WK = Wkv + (size_t)(h * 64) * 256 + ks * 64;

#pragma unroll
    for (int it = 0; it < 4; ++it) {
        const int idx = tid + it * 256;
        const int row = idx >> 4, c4 = idx & 15;
        *reinterpret_cast<float4*>(&s_q[row * FAS + c4 * 4]) =
            *reinterpret_cast<const float4*>(SQ + (size_t)row * 256 + c4 * 4);
        *reinterpret_cast<float4*>(&s_k[row * FAS + c4 * 4]) =
            *reinterpret_cast<const float4*>(WK + (size_t)row * 256 + c4 * 4);
    }
    __syncthreads();

    const int i0 = (tid >> 4) * 4, j0 = (tid & 15) * 4;
    float acc[4][4] = {};
#pragma unroll
    for (int k = 0; k < 64; k += 4) {
        float4 qv[4], kv[4];
#pragma unroll
        for (int a = 0; a < 4; ++a) {
            qv[a] = *reinterpret_cast<const float4*>(&s_q[(i0 + a) * FAS + k]);
            kv[a] = *reinterpret_cast<const float4*>(&s_k[(j0 + a) * FAS + k]);
        }
#pragma unroll
        for (int a = 0; a < 4; ++a)
#pragma unroll
            for (int b = 0; b < 4; ++b)
                acc[a][b] += qv[a].x * kv[b].x + qv[a].y * kv[b].y
                           + qv[a].z * kv[b].z + qv[a].w * kv[b].w;
    }

    float* P = g_simp + (size_t)(gh * 4 + ks) * 4096;
#pragma unroll
    for (int a = 0; a < 4; ++a)
        *reinterpret_cast<float4*>(&P[(i0 + a) * 64 + j0]) =
            make_float4(acc[a][0], acc[a][1], acc[a][2], acc[a][3]);
}

// ---------------------------------------------------------------------------
// Kernel 5: reduce sim partials + scale + softmax. grid (64, 16), 64 thr.
// ---------------------------------------------------------------------------
__global__ void __launch_bounds__(64) softmax_kernel()
{
    const int i  = blockIdx.x;
    const int gh = blockIdx.y;
    const int j  = threadIdx.x;

    float v = 0.f;
#pragma unroll
    for (int ks = 0; ks < 4; ++ks)
        v += g_simp[(size_t)(gh * 4 + ks) * 4096 + i * 64 + j];
    v *= 0.125f;

    __shared__ float s[64];
    __shared__ float red;
    s[j] = v;
    __syncthreads();
    if (j == 0) {
        float m = s[0];
        for (int t = 1; t < 64; ++t) m = fmaxf(m, s[t]);
        red = m;
    }
    __syncthreads();
    const float e = __expf(v - red);
    s[j] = e;
    __syncthreads();
    if (j == 0) {
        float su = 0.f;
        for (int t = 0; t < 64; ++t) su += s[t];
        red = su;
    }
    __syncthreads();
    g_attn[(size_t)gh * 4096 + i * 64 + j] = e / red;
}

// ---------------------------------------------------------------------------
// Kernel 6: U = attn @ Wv. grid (4 ftile, 16 gh). 64x64 out, K=64.
// ---------------------------------------------------------------------------
__global__ void __launch_bounds__(256) u_kernel(const float* __restrict__ Wkv)
{
    __shared__ __align__(16) float s_a[64 * FAS];
    __shared__ __align__(16) float s_w[64 * FAS];

    const int ft = blockIdx.x, gh = blockIdx.y;
    const int g = gh >> 3, h = gh & 7;
    const int tid = threadIdx.x;

    const float* A  = g_attn + (size_t)gh * 4096;
    const float* WV = Wkv + (size_t)(512 + h * 64) * 256 + ft * 64;

#pragma unroll
    for (int it = 0; it < 4; ++it) {
        const int idx = tid + it * 256;
        const int row = idx >> 4, c4 = idx & 15;
        *reinterpret_cast<float4*>(&s_a[row * FAS + c4 * 4]) =
            *reinterpret_cast<const float4*>(A + (size_t)row * 64 + c4 * 4);
        *reinterpret_cast<float4*>(&s_w[row * FAS + c4 * 4]) =
            *reinterpret_cast<const float4*>(WV + (size_t)row * 256 + c4 * 4);
    }
    __syncthreads();

    const int i0 = (tid >> 4) * 4, f0 = (tid & 15) * 4;
    float acc[4][4] = {};
#pragma unroll
    for (int j = 0; j < 64; ++j) {
        const float4 wv = *reinterpret_cast<const float4*>(&s_w[j * FAS + f0]);
        float av[4];
#pragma unroll
        for (int a = 0; a < 4; ++a) av[a] = s_a[(i0 + a) * FAS + j];
#pragma unroll
        for (int a = 0; a < 4; ++a) {
            acc[a][0] += av[a] * wv.x; acc[a][1] += av[a] * wv.y;
            acc[a][2] += av[a] * wv.z; acc[a][3] += av[a] * wv.w;
        }
    }

    float* U = g_u + ((size_t)g * 512 + h * 64) * 256 + ft * 64;
#pragma unroll
    for (int a = 0; a < 4; ++a)
        *reinterpret_cast<float4*>(&U[(size_t)(i0 + a) * 256 + f0]) =
            make_float4(acc[a][0], acc[a][1], acc[a][2], acc[a][3]);
}

// ---------------------------------------------------------------------------
// Kernel 7: W2_g = Wout @ U_g -> fp16 hi/lo (256x256 per group, K=512)
// 4-row tiles, U staged in 32-row chunks with register prefetch. grid (64,2).
// ---------------------------------------------------------------------------
__global__ void __launch_bounds__(256) w2_kernel(const float* __restrict__ Wout)
{
    __shared__ float s_w[4 * 512];
    __shared__ __align__(16) float s_u[32 * 256];

    const int m0 = blockIdx.x * 4, g = blockIdx.y, n = threadIdx.x;
    const float4* Uv = reinterpret_cast<const float4*>(g_u + (size_t)g * 512 * 256);
    float4* su4 = reinterpret_cast<float4*>(s_u);

#pragma unroll
    for (int r = 0; r < 4; ++r) {
        s_w[r * 512 + n]       = Wout[(size_t)(m0 + r) * 512 + n];
        s_w[r * 512 + 256 + n] = Wout[(size_t)(m0 + r) * 512 + 256 + n];
    }

    float4 pre[8];
#pragma unroll
    for (int it = 0; it < 8; ++it)
        pre[it] = Uv[n + it * 256];

    float acc[4] = {};
#pragma unroll 1
    for (int cc = 0; cc < 512; cc += 32) {
        __syncthreads();
#pragma unroll
        for (int it = 0; it < 8; ++it)
            su4[n + it * 256] = pre[it];
        __syncthreads();
        if (cc + 32 < 512) {
            const float4* Un = Uv + (size_t)(cc + 32) * 64;
#pragma unroll
            for (int it = 0; it < 8; ++it)
                pre[it] = Un[n + it * 256];
        }
#pragma unroll
        for (int k = 0; k < 32; ++k) {
            const float uv = s_u[k * 256 + n];
#pragma unroll
            for (int r = 0; r < 4; ++r)
                acc[r] = fmaf(s_w[r * 512 + cc + k], uv, acc[r]);
        }
    }
#pragma unroll
    for (int r = 0; r < 4; ++r) {
        __half hv, lv;
        split_hl(acc[r], hv, lv);
        g_w2_h[((size_t)g * 256 + m0 + r) * 256 + n] = hv;
        g_w2_l[((size_t)g * 256 + m0 + r) * 256 + n] = lv;
    }
}

// ---------------------------------------------------------------------------
// Kernel 8: out_g = W2_g @ Xhi_g + bout  (2-term: (W2hi + W2lo) @ Xhi).
// M=256, N=16384, K=256. Register-prefetch double buffered.
// ---------------------------------------------------------------------------
__global__ void __launch_bounds__(256) final_kernel(const float* __restrict__ bout,
                                                    float* __restrict__ out)
{
    __shared__ __align__(32) __half sAh[128 * SMS2];
    __shared__ __align__(32) __half sAl[128 * SMS2];
    __shared__ __align__(32) __half sBh[32 * OVS];
    __shared__ __align__(32) float  brep[128 * 16];

    const int tid = threadIdx.x;
    const int wid = tid >> 5;
    const int wm = wid >> 2, wn = wid & 3;
    const int p0 = blockIdx.x * 128;
    const int m0 = blockIdx.y * 128;
    const int g  = blockIdx.z;

    const __half* Ah = g_w2_h + (size_t)g * 65536;
    const __half* Al = g_w2_l + (size_t)g * 65536;
    const __half* Xh = g_xh + (size_t)g * 256 * NSEQ;

    const int arow[2] = { (tid) >> 2, (tid + 256) >> 2 };
    const int ac4     = tid & 3;
    const int brow[2] = { (tid) >> 4, (tid + 256) >> 4 };
    const int bc8     = tid & 15;

    for (int r = tid; r < 128; r += 256) {
        const float bv = bout[m0 + r];
#pragma unroll
        for (int c = 0; c < 16; ++c) brep[r * 16 + c] = bv;
    }
    __syncthreads();

    wmma::fragment<wmma::accumulator, 16, 16, 16, float> acc[4][2];
#pragma unroll
    for (int mi = 0; mi < 4; ++mi)
#pragma unroll
        for (int ni = 0; ni < 2; ++ni)
            wmma::load_matrix_sync(acc[mi][ni],
                                   &brep[(wm * 64 + mi * 16) * 16], 16,
                                   wmma::mem_row_major);

    uint4 rAh[2], rAl[2], rBh[2];
#pragma unroll
    for (int it = 0; it < 2; ++it) {
        const size_t ga = (size_t)(m0 + arow[it]) * 256 + ac4 * 8;
        rAh[it] = *reinterpret_cast<const uint4*>(Ah + ga);
        rAl[it] = *reinterpret_cast<const uint4*>(Al + ga);
        const size_t gb = (size_t)brow[it] * NSEQ + p0 + bc8 * 8;
        rBh[it] = *reinterpret_cast<const uint4*>(Xh + gb);
    }

#pragma unroll 1
    for (int kk = 0; kk < 256; kk += 32) {
        __syncthreads();
#pragma unroll
        for (int it = 0; it < 2; ++it) {
            const int soA = arow[it] * SMS2 + ac4 * 8;
            *reinterpret_cast<uint4*>(&sAh[soA]) = rAh[it];
            *reinterpret_cast<uint4*>(&sAl[soA]) = rAl[it];
            const int soB = brow[it] * OVS + bc8 * 8;
            *reinterpret_cast<uint4*>(&sBh[soB]) = rBh[it];
        }
        __syncthreads();

        if (kk + 32 < 256) {
#pragma unroll
            for (int it = 0; it < 2; ++it) {
                const size_t ga = (size_t)(m0 + arow[it]) * 256 + kk + 32 + ac4 * 8;
                rAh[it] = *reinterpret_cast<const uint4*>(Ah + ga);
                rAl[it] = *reinterpret_cast<const uint4*>(Al + ga);
                const size_t gb = (size_t)(kk + 32 + brow[it]) * NSEQ + p0 + bc8 * 8;
                rBh[it] = *reinterpret_cast<const uint4*>(Xh + gb);
            }
        }

#pragma unroll
        for (int k2 = 0; k2 < 2; ++k2) {
            wmma::fragment<wmma::matrix_a, 16, 16, 16, __half, wmma::row_major> fah[4], fal[4];
            wmma::fragment<wmma::matrix_b, 16, 16, 16, __half, wmma::row_major> fbh[2];
#pragma unroll
            for (int mi = 0; mi < 4; ++mi) {
                const int ro = (wm * 64 + mi * 16) * SMS2 + k2 * 16;
                wmma::load_matrix_sync(fah[mi], &sAh[ro], SMS2);
                wmma::load_matrix_sync(fal[mi], &sAl[ro], SMS2);
            }
#pragma unroll
            for (int ni = 0; ni < 2; ++ni) {
                const int co = (k2 * 16) * OVS + wn * 32 + ni * 16;
                wmma::load_matrix_sync(fbh[ni], &sBh[co], OVS);
            }
#pragma unroll
            for (int mi = 0; mi < 4; ++mi)
#pragma unroll
                for (int ni = 0; ni < 2; ++ni) {
                    wmma::mma_sync(acc[mi][ni], fah[mi], fbh[ni], acc[mi][ni]);
                    wmma::mma_sync(acc[mi][ni], fal[mi], fbh[ni], acc[mi][ni]);
                }
        }
    }

    float* C = out + (size_t)g * 256 * NSEQ;
#pragma unroll
    for (int mi = 0; mi < 4; ++mi)
#pragma unroll
        for (int ni = 0; ni < 2; ++ni)
            wmma::store_matrix_sync(
                C + (size_t)(m0 + wm * 64 + mi * 16) * NSEQ + p0 + wn * 32 + ni * 16,
                acc[mi][ni], NSEQ, wmma::mem_row_major);
}

// ---------------------------------------------------------------------------
extern "C" void kernel_launch(void* const* d_in, const int* in_sizes, int n_in,
                              void* d_out, int out_size)
{
    const float* x    = (const float*)d_in[0];
    const float* Wq   = (const float*)d_in[1];
    const float* Wkv  = (const float*)d_in[2];
    const float* Wout = (const float*)d_in[3];
    const float* bout = (const float*)d_in[4];
    float* out = (float*)d_out;
    (void)in_sizes; (void)n_in; (void)out_size;

    convert_x   <<<dim3(256, 2), 256>>>(x);
    gram_kernel <<<dim3(GSP, 3, 2), 256>>>();
    gram_reduce <<<dim3(64, 2), 256>>>();
    sq_kernel   <<<dim3(128, 2), 256>>>(Wq);
    simp_kernel <<<dim3(4, 16), 256>>>(Wkv);
    softmax_kernel<<<dim3(64, 16), 64>>>();
    u_kernel    <<<dim3(4, 16), 256>>>(Wkv);
    w2_kernel   <<<dim3(64, 2), 256>>>(Wout);
    final_kernel<<<dim3(NSEQ / 128, 2, 2), 256>>>(bout, out);
}

// round 16
// speedup vs baseline: 1.7025x; 1.2138x over previous
#include <cuda_runtime.h>
#include <cuda_fp16.h>
#include <mma.h>
#include <cstdint>
#include <cstddef>

using namespace nvcuda;

// x: [16][32][128][128] fp32 == X[2][256][16384] (g, f, p)
// Wq: [512][256], Wkv: [1024][256] (K rows 0..511, V rows 512..1023),
// Wout: [256][512], bout: [256], out: [2][256][16384] fp32
//
//   Xh = fp16(X)                         (convert_x)
//   G_g = Xh_g Xh_g^T  (symmetric,1term) (gram_kernel + gram_reduce)
//   Sq_g = Wq @ G_g                      (sq_kernel)
//   simp = Sq[h] @ Wk[h]^T (k-split)     (simp_kernel)
//   attn = softmax(0.125 * sum simp)     (softmax_kernel)
//   U_g[h] = attn @ Wv[h]                (u_kernel)
//   W2_g = Wout @ U_g -> fp16 hi/lo      (w2_kernel)
//   out_g = W2 @ Xh + bout  (2-term)     (final_kernel)

#define NSEQ 16384
#define SMS2 40    // fp16 staging stride, 32-half rows (+pad)
#define OVS  136   // fp16 staging stride, 128-half rows (+pad)
#define GSP  32    // gram k-splits
#define FAS  68    // fp32 staging stride (floats), 64-wide tiles

// ------------------------------ scratch ------------------------------------
__device__ __half g_xh  [(size_t)2 * 256 * 16384];      // X hi
__device__ float  g_gpart[(size_t)2 * GSP * 256 * 256]; // gram partials
__device__ float  g_gram [(size_t)2 * 256 * 256];
__device__ float  g_sq   [(size_t)2 * 512 * 256];
__device__ float  g_simp [(size_t)16 * 4 * 64 * 64];    // sim k-split partials
__device__ float  g_attn [(size_t)16 * 64 * 64];
__device__ float  g_u    [(size_t)2 * 512 * 256];
__device__ __half g_w2_h [(size_t)2 * 256 * 256];
__device__ __half g_w2_l [(size_t)2 * 256 * 256];

__device__ __forceinline__ void split_hl(float v, __half& hi, __half& lo) {
    hi = __float2half_rn(v);
    lo = __float2half_rn(v - __half2float(hi));
}

// ---------------------------------------------------------------------------
// Kernel 0: X fp32 -> Xh fp16 (same [g][f][p] layout)
// ---------------------------------------------------------------------------
__global__ void __launch_bounds__(256) convert_x(const float* __restrict__ x)
{
    const size_t base = ((size_t)blockIdx.y * 256 + blockIdx.x) * NSEQ;
    const float4* src = reinterpret_cast<const float4*>(x + base);
    uint4* dh = reinterpret_cast<uint4*>(g_xh + base);
    for (int t = threadIdx.x; t < 2048; t += 256) {
        const float4 v0 = src[2 * t], v1 = src[2 * t + 1];
        __half h[8];
        h[0] = __float2half_rn(v0.x); h[1] = __float2half_rn(v0.y);
        h[2] = __float2half_rn(v0.z); h[3] = __float2half_rn(v0.w);
        h[4] = __float2half_rn(v1.x); h[5] = __float2half_rn(v1.y);
        h[6] = __float2half_rn(v1.z); h[7] = __float2half_rn(v1.w);
        dh[t] = *reinterpret_cast<uint4*>(h);
    }
}

// ---------------------------------------------------------------------------
// Kernel 1: gram partials (symmetric, 1-term Xh*Xh^T), register-prefetch.
// blockIdx.y: 0->(0,0), 1->(1,0), 2->(1,1). 128x128 tile, 512 p per k-split.
// ---------------------------------------------------------------------------
__global__ void __launch_bounds__(256) gram_kernel()
{
    __shared__ __align__(32) __half sAh[128 * SMS2];
    __shared__ __align__(32) __half sBh[128 * SMS2];

    const int ks = blockIdx.x;
    const int y  = blockIdx.y;
    const int g  = blockIdx.z;
    const int tm = (y >= 1), tn = (y == 2);
    const bool diag = (tm == tn);
    const int p0 = ks * 512;

    const __half* Xh = g_xh + (size_t)g * 256 * NSEQ;

    const int tid = threadIdx.x;
    const int wid = tid >> 5;
    const int wm = wid >> 2, wn = wid & 3;
    const int lc4  = tid & 3;
    const int rows[2] = { (tid) >> 2, (tid + 256) >> 2 };

    wmma::fragment<wmma::accumulator, 16, 16, 16, float> acc[4][2];
#pragma unroll
    for (int mi = 0; mi < 4; ++mi)
#pragma unroll
        for (int ni = 0; ni < 2; ++ni) wmma::fill_fragment(acc[mi][ni], 0.0f);

    const __half* pBh = diag ? sAh : sBh;

    uint4 rAh[2], rBh[2];
#pragma unroll
    for (int it = 0; it < 2; ++it) {
        const size_t ga = (size_t)(tm * 128 + rows[it]) * NSEQ + p0 + lc4 * 8;
        rAh[it] = *reinterpret_cast<const uint4*>(Xh + ga);
        if (!diag) {
            const size_t gb = (size_t)(tn * 128 + rows[it]) * NSEQ + p0 + lc4 * 8;
            rBh[it] = *reinterpret_cast<const uint4*>(Xh + gb);
        }
    }

#pragma unroll 1
    for (int pc = 0; pc < 512; pc += 32) {
        __syncthreads();
#pragma unroll
        for (int it = 0; it < 2; ++it) {
            const int so = rows[it] * SMS2 + lc4 * 8;
            *reinterpret_cast<uint4*>(&sAh[so]) = rAh[it];
            if (!diag)
                *reinterpret_cast<uint4*>(&sBh[so]) = rBh[it];
        }
        __syncthreads();

        if (pc + 32 < 512) {
#pragma unroll
            for (int it = 0; it < 2; ++it) {
                const size_t ga = (size_t)(tm * 128 + rows[it]) * NSEQ
                                + p0 + pc + 32 + lc4 * 8;
                rAh[it] = *reinterpret_cast<const uint4*>(Xh + ga);
                if (!diag) {
                    const size_t gb = (size_t)(tn * 128 + rows[it]) * NSEQ
                                    + p0 + pc + 32 + lc4 * 8;
                    rBh[it] = *reinterpret_cast<const uint4*>(Xh + gb);
                }
            }
        }

#pragma unroll
        for (int k2 = 0; k2 < 2; ++k2) {
            wmma::fragment<wmma::matrix_a, 16, 16, 16, __half, wmma::row_major> fah[4];
            wmma::fragment<wmma::matrix_b, 16, 16, 16, __half, wmma::col_major> fbh[2];
#pragma unroll
            for (int mi = 0; mi < 4; ++mi)
                wmma::load_matrix_sync(fah[mi], &sAh[(wm * 64 + mi * 16) * SMS2 + k2 * 16], SMS2);
#pragma unroll
            for (int ni = 0; ni < 2; ++ni)
                wmma::load_matrix_sync(fbh[ni], &pBh[(wn * 32 + ni * 16) * SMS2 + k2 * 16], SMS2);
#pragma unroll
            for (int mi = 0; mi < 4; ++mi)
#pragma unroll
                for (int ni = 0; ni < 2; ++ni)
                    wmma::mma_sync(acc[mi][ni], fah[mi], fbh[ni], acc[mi][ni]);
        }
    }

    float* P = g_gpart + (size_t)(g * GSP + ks) * 65536;
#pragma unroll
    for (int mi = 0; mi < 4; ++mi)
#pragma unroll
        for (int ni = 0; ni < 2; ++ni) {
            const int rb = tm * 128 + wm * 64 + mi * 16;
            const int cb = tn * 128 + wn * 32 + ni * 16;
            wmma::store_matrix_sync(P + (size_t)rb * 256 + cb, acc[mi][ni],
                                    256, wmma::mem_row_major);
            if (tm != tn)
                wmma::store_matrix_sync(P + (size_t)cb * 256 + rb, acc[mi][ni],
                                        256, wmma::mem_col_major);
        }
}

// ---------------------------------------------------------------------------
// Kernel 2: reduce gram partials (float4 vectorized). grid (64, 2).
// ---------------------------------------------------------------------------
__global__ void __launch_bounds__(256) gram_reduce()
{
    const int g = blockIdx.y;
    const int idx = blockIdx.x * 256 + threadIdx.x;   // float4 index 0..16383
    const float4* P = reinterpret_cast<const float4*>(g_gpart) + (size_t)g * GSP * 16384;
    float4 s = make_float4(0.f, 0.f, 0.f, 0.f);
#pragma unroll 8
    for (int ks = 0; ks < GSP; ++ks) {
        const float4 v = P[(size_t)ks * 16384 + idx];
        s.x += v.x; s.y += v.y; s.z += v.z; s.w += v.w;
    }
    reinterpret_cast<float4*>(g_gram)[(size_t)g * 16384 + idx] = s;
}

// ---------------------------------------------------------------------------
// Kernel 3: Sq_g = Wq @ G_g  (512x256 per group, K=256, fp32)
// 4-row tiles, G staged in 32-row chunks with register prefetch. grid (128,2).
// ---------------------------------------------------------------------------
__global__ void __launch_bounds__(256) sq_kernel(const float* __restrict__ Wq)
{
    __shared__ float s_w[4 * 256];
    __shared__ __align__(16) float s_g[32 * 256];

    const int m0 = blockIdx.x * 4, g = blockIdx.y, n = threadIdx.x;
    const float4* Gv = reinterpret_cast<const float4*>(g_gram + (size_t)g * 65536);
    float4* sg4 = reinterpret_cast<float4*>(s_g);

#pragma unroll
    for (int r = 0; r < 4; ++r)
        s_w[r * 256 + n] = Wq[(size_t)(m0 + r) * 256 + n];

    float4 pre[8];
#pragma unroll
    for (int it = 0; it < 8; ++it)
        pre[it] = Gv[n + it * 256];

    float acc[4] = {};
#pragma unroll 1
    for (int kc = 0; kc < 256; kc += 32) {
        __syncthreads();
#pragma unroll
        for (int it = 0; it < 8; ++it)
            sg4[n + it * 256] = pre[it];
        __syncthreads();
        if (kc + 32 < 256) {
            const float4* Gn = Gv + (size_t)(kc + 32) * 64;
#pragma unroll
            for (int it = 0; it < 8; ++it)
                pre[it] = Gn[n + it * 256];
        }
#pragma unroll
        for (int k = 0; k < 32; ++k) {
            const float gv = s_g[k * 256 + n];
#pragma unroll
            for (int r = 0; r < 4; ++r)
                acc[r] = fmaf(s_w[r * 256 + kc + k], gv, acc[r]);
        }
    }
#pragma unroll
    for (int r = 0; r < 4; ++r)
        g_sq[((size_t)g * 512 + m0 + r) * 256 + n] = acc[r];
}

// ---------------------------------------------------------------------------
// Kernel 4: sim partials. grid (4 ksplit, 16 gh). 64x64 out, K=64 per block.
// ---------------------------------------------------------------------------
__global__ void __launch_bounds__(256) simp_kernel(const float* __restrict__ Wkv)
{
    __shared__ __align__(16) float s_q[64 * FAS];
    __shared__ __align__(16) float s_k[64 * FAS];

    const int ks = blockIdx.x, gh = blockIdx.y;
    const int g = gh >> 3, h = gh & 7;
    const int tid = threadIdx.x;

    const float* SQ = g_sq + ((size_t)g * 512 + h * 64) * 256 + ks * 64;
    const float* WK = Wkv + (size_t)(h * 64) * 256 + ks * 64;

#pragma unroll
    for (int it = 0; it < 4; ++it) {
        const int idx = tid + it * 256;
        const int row = idx >> 4, c4 = idx & 15;
        *reinterpret_cast<float4*>(&s_q[row * FAS + c4 * 4]) =
            *reinterpret_cast<const float4*>(SQ + (size_t)row * 256 + c4 * 4);
        *reinterpret_cast<float4*>(&s_k[row * FAS + c4 * 4]) =
            *reinterpret_cast<const float4*>(WK + (size_t)row * 256 + c4 * 4);
    }
    __syncthreads();

    const int i0 = (tid >> 4) * 4, j0 = (tid & 15) * 4;
    float acc[4][4] = {};
#pragma unroll
    for (int k = 0; k < 64; k += 4) {
        float4 qv[4], kv[4];
#pragma unroll
        for (int a = 0; a < 4; ++a) {
            qv[a] = *reinterpret_cast<const float4*>(&s_q[(i0 + a) * FAS + k]);
            kv[a] = *reinterpret_cast<const float4*>(&s_k[(j0 + a) * FAS + k]);
        }
#pragma unroll
        for (int a = 0; a < 4; ++a)
#pragma unroll
            for (int b = 0; b < 4; ++b)
                acc[a][b] += qv[a].x * kv[b].x + qv[a].y * kv[b].y
                           + qv[a].z * kv[b].z + qv[a].w * kv[b].w;
    }

    float* P = g_simp + (size_t)(gh * 4 + ks) * 4096;
#pragma unroll
    for (int a = 0; a < 4; ++a)
        *reinterpret_cast<float4*>(&P[(i0 + a) * 64 + j0]) =
            make_float4(acc[a][0], acc[a][1], acc[a][2], acc[a][3]);
}

// ---------------------------------------------------------------------------
// Kernel 5: reduce sim partials + scale + softmax. grid (64, 16), 64 thr.
// ---------------------------------------------------------------------------
__global__ void __launch_bounds__(64) softmax_kernel()
{
    const int i  = blockIdx.x;
    const int gh = blockIdx.y;
    const int j  = threadIdx.x;

    float v = 0.f;
#pragma unroll
    for (int ks = 0; ks < 4; ++ks)
        v += g_simp[(size_t)(gh * 4 + ks) * 4096 + i * 64 + j];
    v *= 0.125f;

    __shared__ float s[64];
    __shared__ float red;
    s[j] = v;
    __syncthreads();
    if (j == 0) {
        float m = s[0];
        for (int t = 1; t < 64; ++t) m = fmaxf(m, s[t]);
        red = m;
    }
    __syncthreads();
    const float e = __expf(v - red);
    s[j] = e;
    __syncthreads();
    if (j == 0) {
        float su = 0.f;
        for (int t = 0; t < 64; ++t) su += s[t];
        red = su;
    }
    __syncthreads();
    g_attn[(size_t)gh * 4096 + i * 64 + j] = e / red;
}

// ---------------------------------------------------------------------------
// Kernel 6: U = attn @ Wv. grid (4 ftile, 16 gh). 64x64 out, K=64.
// ---------------------------------------------------------------------------
__global__ void __launch_bounds__(256) u_kernel(const float* __restrict__ Wkv)
{
    __shared__ __align__(16) float s_a[64 * FAS];
    __shared__ __align__(16) float s_w[64 * FAS];

    const int ft = blockIdx.x, gh = blockIdx.y;
    const int g = gh >> 3, h = gh & 7;
    const int tid = threadIdx.x;

    const float* A  = g_attn + (size_t)gh * 4096;
    const float* WV = Wkv + (size_t)(512 + h * 64) * 256 + ft * 64;

#pragma unroll
    for (int it = 0; it < 4; ++it) {
        const int idx = tid + it * 256;
        const int row = idx >> 4, c4 = idx & 15;
        *reinterpret_cast<float4*>(&s_a[row * FAS + c4 * 4]) =
            *reinterpret_cast<const float4*>(A + (size_t)row * 64 + c4 * 4);
        *reinterpret_cast<float4*>(&s_w[row * FAS + c4 * 4]) =
            *reinterpret_cast<const float4*>(WV + (size_t)row * 256 + c4 * 4);
    }
    __syncthreads();

    const int i0 = (tid >> 4) * 4, f0 = (tid & 15) * 4;
    float acc[4][4] = {};
#pragma unroll
    for (int j = 0; j < 64; ++j) {
        const float4 wv = *reinterpret_cast<const float4*>(&s_w[j * FAS + f0]);
        float av[4];
#pragma unroll
        for (int a = 0; a < 4; ++a) av[a] = s_a[(i0 + a) * FAS + j];
#pragma unroll
        for (int a = 0; a < 4; ++a) {
            acc[a][0] += av[a] * wv.x; acc[a][1] += av[a] * wv.y;
            acc[a][2] += av[a] * wv.z; acc[a][3] += av[a] * wv.w;
        }
    }

    float* U = g_u + ((size_t)g * 512 + h * 64) * 256 + ft * 64;
#pragma unroll
    for (int a = 0; a < 4; ++a)
        *reinterpret_cast<float4*>(&U[(size_t)(i0 + a) * 256 + f0]) =
            make_float4(acc[a][0], acc[a][1], acc[a][2], acc[a][3]);
}

// ---------------------------------------------------------------------------
// Kernel 7: W2_g = Wout @ U_g -> fp16 hi/lo (256x256 per group, K=512)
// 4-row tiles, U staged in 32-row chunks with register prefetch. grid (64,2).
// ---------------------------------------------------------------------------
__global__ void __launch_bounds__(256) w2_kernel(const float* __restrict__ Wout)
{
    __shared__ float s_w[4 * 512];
    __shared__ __align__(16) float s_u[32 * 256];

    const int m0 = blockIdx.x * 4, g = blockIdx.y, n = threadIdx.x;
    const float4* Uv = reinterpret_cast<const float4*>(g_u + (size_t)g * 512 * 256);
    float4* su4 = reinterpret_cast<float4*>(s_u);

#pragma unroll
    for (int r = 0; r < 4; ++r) {
        s_w[r * 512 + n]       = Wout[(size_t)(m0 + r) * 512 + n];
        s_w[r * 512 + 256 + n] = Wout[(size_t)(m0 + r) * 512 + 256 + n];
    }

    float4 pre[8];
#pragma unroll
    for (int it = 0; it < 8; ++it)
        pre[it] = Uv[n + it * 256];

    float acc[4] = {};
#pragma unroll 1
    for (int cc = 0; cc < 512; cc += 32) {
        __syncthreads();
#pragma unroll
        for (int it = 0; it < 8; ++it)
            su4[n + it * 256] = pre[it];
        __syncthreads();
        if (cc + 32 < 512) {
            const float4* Un = Uv + (size_t)(cc + 32) * 64;
#pragma unroll
            for (int it = 0; it < 8; ++it)
                pre[it] = Un[n + it * 256];
        }
#pragma unroll
        for (int k = 0; k < 32; ++k) {
            const float uv = s_u[k * 256 + n];
#pragma unroll
            for (int r = 0; r < 4; ++r)
                acc[r] = fmaf(s_w[r * 512 + cc + k], uv, acc[r]);
        }
    }
#pragma unroll
    for (int r = 0; r < 4; ++r) {
        __half hv, lv;
        split_hl(acc[r], hv, lv);
        g_w2_h[((size_t)g * 256 + m0 + r) * 256 + n] = hv;
        g_w2_l[((size_t)g * 256 + m0 + r) * 256 + n] = lv;
    }
}

// ---------------------------------------------------------------------------
// Kernel 8: out_g = W2_g @ Xh_g + bout  (2-term: (W2hi + W2lo) @ Xh).
// M=256, N=16384, K=256. Register-prefetch double buffered.
// ---------------------------------------------------------------------------
__global__ void __launch_bounds__(256) final_kernel(const float* __restrict__ bout,
                                                    float* __restrict__ out)
{
    __shared__ __align__(32) __half sAh[128 * SMS2];
    __shared__ __align__(32) __half sAl[128 * SMS2];
    __shared__ __align__(32) __half sBh[32 * OVS];
    __shared__ __align__(32) float  brep[128 * 16];

    const int tid = threadIdx.x;
    const int wid = tid >> 5;
    const int wm = wid >> 2, wn = wid & 3;
    const int p0 = blockIdx.x * 128;
    const int m0 = blockIdx.y * 128;
    const int g  = blockIdx.z;

    const __half* Ah = g_w2_h + (size_t)g * 65536;
    const __half* Al = g_w2_l + (size_t)g * 65536;
    const __half* Xh = g_xh + (size_t)g * 256 * NSEQ;

    const int arow[2] = { (tid) >> 2, (tid + 256) >> 2 };
    const int ac4     = tid & 3;
    const int brow[2] = { (tid) >> 4, (tid + 256) >> 4 };
    const int bc8     = tid & 15;

    for (int r = tid; r < 128; r += 256) {
        const float bv = bout[m0 + r];
#pragma unroll
        for (int c = 0; c < 16; ++c) brep[r * 16 + c] = bv;
    }
    __syncthreads();

    wmma::fragment<wmma::accumulator, 16, 16, 16, float> acc[4][2];
#pragma unroll
    for (int mi = 0; mi < 4; ++mi)
#pragma unroll
        for (int ni = 0; ni < 2; ++ni)
            wmma::load_matrix_sync(acc[mi][ni],
                                   &brep[(wm * 64 + mi * 16) * 16], 16,
                                   wmma::mem_row_major);

    uint4 rAh[2], rAl[2], rBh[2];
#pragma unroll
    for (int it = 0; it < 2; ++it) {
        const size_t ga = (size_t)(m0 + arow[it]) * 256 + ac4 * 8;
        rAh[it] = *reinterpret_cast<const uint4*>(Ah + ga);
        rAl[it] = *reinterpret_cast<const uint4*>(Al + ga);
        const size_t gb = (size_t)brow[it] * NSEQ + p0 + bc8 * 8;
        rBh[it] = *reinterpret_cast<const uint4*>(Xh + gb);
    }

#pragma unroll 1
    for (int kk = 0; kk < 256; kk += 32) {
        __syncthreads();
#pragma unroll
        for (int it = 0; it < 2; ++it) {
            const int soA = arow[it] * SMS2 + ac4 * 8;
            *reinterpret_cast<uint4*>(&sAh[soA]) = rAh[it];
            *reinterpret_cast<uint4*>(&sAl[soA]) = rAl[it];
            const int soB = brow[it] * OVS + bc8 * 8;
            *reinterpret_cast<uint4*>(&sBh[soB]) = rBh[it];
        }
        __syncthreads();

        if (kk + 32 < 256) {
#pragma unroll
            for (int it = 0; it < 2; ++it) {
                const size_t ga = (size_t)(m0 + arow[it]) * 256 + kk + 32 + ac4 * 8;
                rAh[it] = *reinterpret_cast<const uint4*>(Ah + ga);
                rAl[it] = *reinterpret_cast<const uint4*>(Al + ga);
                const size_t gb = (size_t)(kk + 32 + brow[it]) * NSEQ + p0 + bc8 * 8;
                rBh[it] = *reinterpret_cast<const uint4*>(Xh + gb);
            }
        }

#pragma unroll
        for (int k2 = 0; k2 < 2; ++k2) {
            wmma::fragment<wmma::matrix_a, 16, 16, 16, __half, wmma::row_major> fah[4], fal[4];
            wmma::fragment<wmma::matrix_b, 16, 16, 16, __half, wmma::row_major> fbh[2];
#pragma unroll
            for (int mi = 0; mi < 4; ++mi) {
                const int ro = (wm * 64 + mi * 16) * SMS2 + k2 * 16;
                wmma::load_matrix_sync(fah[mi], &sAh[ro], SMS2);
                wmma::load_matrix_sync(fal[mi], &sAl[ro], SMS2);
            }
#pragma unroll
            for (int ni = 0; ni < 2; ++ni) {
                const int co = (k2 * 16) * OVS + wn * 32 + ni * 16;
                wmma::load_matrix_sync(fbh[ni], &sBh[co], OVS);
            }
#pragma unroll
            for (int mi = 0; mi < 4; ++mi)
#pragma unroll
                for (int ni = 0; ni < 2; ++ni) {
                    wmma::mma_sync(acc[mi][ni], fah[mi], fbh[ni], acc[mi][ni]);
                    wmma::mma_sync(acc[mi][ni], fal[mi], fbh[ni], acc[mi][ni]);
                }
        }
    }

    float* C = out + (size_t)g * 256 * NSEQ;
#pragma unroll
    for (int mi = 0; mi < 4; ++mi)
#pragma unroll
        for (int ni = 0; ni < 2; ++ni)
            wmma::store_matrix_sync(
                C + (size_t)(m0 + wm * 64 + mi * 16) * NSEQ + p0 + wn * 32 + ni * 16,
                acc[mi][ni], NSEQ, wmma::mem_row_major);
}

// ---------------------------------------------------------------------------
extern "C" void kernel_launch(void* const* d_in, const int* in_sizes, int n_in,
                              void* d_out, int out_size)
{
    const float* x    = (const float*)d_in[0];
    const float* Wq   = (const float*)d_in[1];
    const float* Wkv  = (const float*)d_in[2];
    const float* Wout = (const float*)d_in[3];
    const float* bout = (const float*)d_in[4];
    float* out = (float*)d_out;
    (void)in_sizes; (void)n_in; (void)out_size;

    convert_x   <<<dim3(256, 2), 256>>>(x);
    gram_kernel <<<dim3(GSP, 3, 2), 256>>>();
    gram_reduce <<<dim3(64, 2), 256>>>();
    sq_kernel   <<<dim3(128, 2), 256>>>(Wq);
    simp_kernel <<<dim3(4, 16), 256>>>(Wkv);
    softmax_kernel<<<dim3(64, 16), 64>>>();
    u_kernel    <<<dim3(4, 16), 256>>>(Wkv);
    w2_kernel   <<<dim3(64, 2), 256>>>(Wout);
    final_kernel<<<dim3(NSEQ / 128, 2, 2), 256>>>(bout, out);
}

// round 17
// speedup vs baseline: 1.9719x; 1.1583x over previous
#include <cuda_runtime.h>
#include <cuda_fp16.h>
#include <mma.h>
#include <cstdint>
#include <cstddef>

using namespace nvcuda;

// x: [16][32][128][128] fp32 == X[2][256][16384] (g, f, p)
// Wq: [512][256], Wkv: [1024][256] (K rows 0..511, V rows 512..1023),
// Wout: [256][512], bout: [256], out: [2][256][16384] fp32
//
//   Xh = fp16(X)                         (convert_x)
//   G_g = Xh_g Xh_g^T  (symmetric,1term) (gram_kernel + gram_reduce)
//   Sq_g = Wq @ G_g                      (sq_kernel)
//   simp = Sq[h] @ Wk[h]^T (k-split)     (simp_kernel)
//   attn = softmax(0.125 * sum simp)     (softmax_kernel)
//   U_g[h] = attn @ Wv[h]                (u_kernel)
//   W2_g = fp16(Wout @ U_g)              (w2_kernel)
//   out_g = W2 @ Xh + bout  (1-term)     (final_kernel)

#define NSEQ 16384
#define SMS2 40    // fp16 staging stride, 32-half rows (+pad)
#define OVS  136   // fp16 staging stride, 128-half rows (+pad)
#define GSP  32    // gram k-splits
#define FAS  68    // fp32 staging stride (floats), 64-wide tiles

// ------------------------------ scratch ------------------------------------
__device__ __half g_xh  [(size_t)2 * 256 * 16384];      // X hi
__device__ float  g_gpart[(size_t)2 * GSP * 256 * 256]; // gram partials
__device__ float  g_gram [(size_t)2 * 256 * 256];
__device__ float  g_sq   [(size_t)2 * 512 * 256];
__device__ float  g_simp [(size_t)16 * 4 * 64 * 64];    // sim k-split partials
__device__ float  g_attn [(size_t)16 * 64 * 64];
__device__ float  g_u    [(size_t)2 * 512 * 256];
__device__ __half g_w2_h [(size_t)2 * 256 * 256];

// ---------------------------------------------------------------------------
// Kernel 0: X fp32 -> Xh fp16 (same [g][f][p] layout)
// ---------------------------------------------------------------------------
__global__ void __launch_bounds__(256) convert_x(const float* __restrict__ x)
{
    const size_t base = ((size_t)blockIdx.y * 256 + blockIdx.x) * NSEQ;
    const float4* src = reinterpret_cast<const float4*>(x + base);
    uint4* dh = reinterpret_cast<uint4*>(g_xh + base);
    for (int t = threadIdx.x; t < 2048; t += 256) {
        const float4 v0 = src[2 * t], v1 = src[2 * t + 1];
        __half h[8];
        h[0] = __float2half_rn(v0.x); h[1] = __float2half_rn(v0.y);
        h[2] = __float2half_rn(v0.z); h[3] = __float2half_rn(v0.w);
        h[4] = __float2half_rn(v1.x); h[5] = __float2half_rn(v1.y);
        h[6] = __float2half_rn(v1.z); h[7] = __float2half_rn(v1.w);
        dh[t] = *reinterpret_cast<uint4*>(h);
    }
}

// ---------------------------------------------------------------------------
// Kernel 1: gram partials (symmetric, 1-term Xh*Xh^T), register-prefetch.
// blockIdx.y: 0->(0,0), 1->(1,0), 2->(1,1). 128x128 tile, 512 p per k-split.
// ---------------------------------------------------------------------------
__global__ void __launch_bounds__(256) gram_kernel()
{
    __shared__ __align__(32) __half sAh[128 * SMS2];
    __shared__ __align__(32) __half sBh[128 * SMS2];

    const int ks = blockIdx.x;
    const int y  = blockIdx.y;
    const int g  = blockIdx.z;
    const int tm = (y >= 1), tn = (y == 2);
    const bool diag = (tm == tn);
    const int p0 = ks * 512;

    const __half* Xh = g_xh + (size_t)g * 256 * NSEQ;

    const int tid = threadIdx.x;
    const int wid = tid >> 5;
    const int wm = wid >> 2, wn = wid & 3;
    const int lc4  = tid & 3;
    const int rows[2] = { (tid) >> 2, (tid + 256) >> 2 };

    wmma::fragment<wmma::accumulator, 16, 16, 16, float> acc[4][2];
#pragma unroll
    for (int mi = 0; mi < 4; ++mi)
#pragma unroll
        for (int ni = 0; ni < 2; ++ni) wmma::fill_fragment(acc[mi][ni], 0.0f);

    const __half* pBh = diag ? sAh : sBh;

    uint4 rAh[2], rBh[2];
#pragma unroll
    for (int it = 0; it < 2; ++it) {
        const size_t ga = (size_t)(tm * 128 + rows[it]) * NSEQ + p0 + lc4 * 8;
        rAh[it] = *reinterpret_cast<const uint4*>(Xh + ga);
        if (!diag) {
            const size_t gb = (size_t)(tn * 128 + rows[it]) * NSEQ + p0 + lc4 * 8;
            rBh[it] = *reinterpret_cast<const uint4*>(Xh + gb);
        }
    }

#pragma unroll 1
    for (int pc = 0; pc < 512; pc += 32) {
        __syncthreads();
#pragma unroll
        for (int it = 0; it < 2; ++it) {
            const int so = rows[it] * SMS2 + lc4 * 8;
            *reinterpret_cast<uint4*>(&sAh[so]) = rAh[it];
            if (!diag)
                *reinterpret_cast<uint4*>(&sBh[so]) = rBh[it];
        }
        __syncthreads();

        if (pc + 32 < 512) {
#pragma unroll
            for (int it = 0; it < 2; ++it) {
                const size_t ga = (size_t)(tm * 128 + rows[it]) * NSEQ
                                + p0 + pc + 32 + lc4 * 8;
                rAh[it] = *reinterpret_cast<const uint4*>(Xh + ga);
                if (!diag) {
                    const size_t gb = (size_t)(tn * 128 + rows[it]) * NSEQ
                                    + p0 + pc + 32 + lc4 * 8;
                    rBh[it] = *reinterpret_cast<const uint4*>(Xh + gb);
                }
            }
        }

#pragma unroll
        for (int k2 = 0; k2 < 2; ++k2) {
            wmma::fragment<wmma::matrix_a, 16, 16, 16, __half, wmma::row_major> fah[4];
            wmma::fragment<wmma::matrix_b, 16, 16, 16, __half, wmma::col_major> fbh[2];
#pragma unroll
            for (int mi = 0; mi < 4; ++mi)
                wmma::load_matrix_sync(fah[mi], &sAh[(wm * 64 + mi * 16) * SMS2 + k2 * 16], SMS2);
#pragma unroll
            for (int ni = 0; ni < 2; ++ni)
                wmma::load_matrix_sync(fbh[ni], &pBh[(wn * 32 + ni * 16) * SMS2 + k2 * 16], SMS2);
#pragma unroll
            for (int mi = 0; mi < 4; ++mi)
#pragma unroll
                for (int ni = 0; ni < 2; ++ni)
                    wmma::mma_sync(acc[mi][ni], fah[mi], fbh[ni], acc[mi][ni]);
        }
    }

    float* P = g_gpart + (size_t)(g * GSP + ks) * 65536;
#pragma unroll
    for (int mi = 0; mi < 4; ++mi)
#pragma unroll
        for (int ni = 0; ni < 2; ++ni) {
            const int rb = tm * 128 + wm * 64 + mi * 16;
            const int cb = tn * 128 + wn * 32 + ni * 16;
            wmma::store_matrix_sync(P + (size_t)rb * 256 + cb, acc[mi][ni],
                                    256, wmma::mem_row_major);
            if (tm != tn)
                wmma::store_matrix_sync(P + (size_t)cb * 256 + rb, acc[mi][ni],
                                        256, wmma::mem_col_major);
        }
}

// ---------------------------------------------------------------------------
// Kernel 2: reduce gram partials (float4 vectorized). grid (64, 2).
// ---------------------------------------------------------------------------
__global__ void __launch_bounds__(256) gram_reduce()
{
    const int g = blockIdx.y;
    const int idx = blockIdx.x * 256 + threadIdx.x;   // float4 index 0..16383
    const float4* P = reinterpret_cast<const float4*>(g_gpart) + (size_t)g * GSP * 16384;
    float4 s = make_float4(0.f, 0.f, 0.f, 0.f);
#pragma unroll 8
    for (int ks = 0; ks < GSP; ++ks) {
        const float4 v = P[(size_t)ks * 16384 + idx];
        s.x += v.x; s.y += v.y; s.z += v.z; s.w += v.w;
    }
    reinterpret_cast<float4*>(g_gram)[(size_t)g * 16384 + idx] = s;
}

// ---------------------------------------------------------------------------
// Kernel 3: Sq_g = Wq @ G_g  (512x256 per group, K=256, fp32)
// 4-row tiles, G staged in 32-row chunks with register prefetch. grid (128,2).
// ---------------------------------------------------------------------------
__global__ void __launch_bounds__(256) sq_kernel(const float* __restrict__ Wq)
{
    __shared__ float s_w[4 * 256];
    __shared__ __align__(16) float s_g[32 * 256];

    const int m0 = blockIdx.x * 4, g = blockIdx.y, n = threadIdx.x;
    const float4* Gv = reinterpret_cast<const float4*>(g_gram + (size_t)g * 65536);
    float4* sg4 = reinterpret_cast<float4*>(s_g);

#pragma unroll
    for (int r = 0; r < 4; ++r)
        s_w[r * 256 + n] = Wq[(size_t)(m0 + r) * 256 + n];

    float4 pre[8];
#pragma unroll
    for (int it = 0; it < 8; ++it)
        pre[it] = Gv[n + it * 256];

    float acc[4] = {};
#pragma unroll 1
    for (int kc = 0; kc < 256; kc += 32) {
        __syncthreads();
#pragma unroll
        for (int it = 0; it < 8; ++it)
            sg4[n + it * 256] = pre[it];
        __syncthreads();
        if (kc + 32 < 256) {
            const float4* Gn = Gv + (size_t)(kc + 32) * 64;
#pragma unroll
            for (int it = 0; it < 8; ++it)
                pre[it] = Gn[n + it * 256];
        }
#pragma unroll
        for (int k = 0; k < 32; ++k) {
            const float gv = s_g[k * 256 + n];
#pragma unroll
            for (int r = 0; r < 4; ++r)
                acc[r] = fmaf(s_w[r * 256 + kc + k], gv, acc[r]);
        }
    }
#pragma unroll
    for (int r = 0; r < 4; ++r)
        g_sq[((size_t)g * 512 + m0 + r) * 256 + n] = acc[r];
}

// ---------------------------------------------------------------------------
// Kernel 4: sim partials. grid (4 ksplit, 16 gh). 64x64 out, K=64 per block.
// ---------------------------------------------------------------------------
__global__ void __launch_bounds__(256) simp_kernel(const float* __restrict__ Wkv)
{
    __shared__ __align__(16) float s_q[64 * FAS];
    __shared__ __align__(16) float s_k[64 * FAS];

    const int ks = blockIdx.x, gh = blockIdx.y;
    const int g = gh >> 3, h = gh & 7;
    const int tid = threadIdx.x;

    const float* SQ = g_sq + ((size_t)g * 512 + h * 64) * 256 + ks * 64;
    const float* WK = Wkv + (size_t)(h * 64) * 256 + ks * 64;

#pragma unroll
    for (int it = 0; it < 4; ++it) {
        const int idx = tid + it * 256;
        const int row = idx >> 4, c4 = idx & 15;
        *reinterpret_cast<float4*>(&s_q[row * FAS + c4 * 4]) =
            *reinterpret_cast<const float4*>(SQ + (size_t)row * 256 + c4 * 4);
        *reinterpret_cast<float4*>(&s_k[row * FAS + c4 * 4]) =
            *reinterpret_cast<const float4*>(WK + (size_t)row * 256 + c4 * 4);
    }
    __syncthreads();

    const int i0 = (tid >> 4) * 4, j0 = (tid & 15) * 4;
    float acc[4][4] = {};
#pragma unroll
    for (int k = 0; k < 64; k += 4) {
        float4 qv[4], kv[4];
#pragma unroll
        for (int a = 0; a < 4; ++a) {
            qv[a] = *reinterpret_cast<const float4*>(&s_q[(i0 + a) * FAS + k]);
            kv[a] = *reinterpret_cast<const float4*>(&s_k[(j0 + a) * FAS + k]);
        }
#pragma unroll
        for (int a = 0; a < 4; ++a)
#pragma unroll
            for (int b = 0; b < 4; ++b)
                acc[a][b] += qv[a].x * kv[b].x + qv[a].y * kv[b].y
                           + qv[a].z * kv[b].z + qv[a].w * kv[b].w;
    }

    float* P = g_simp + (size_t)(gh * 4 + ks) * 4096;
#pragma unroll
    for (int a = 0; a < 4; ++a)
        *reinterpret_cast<float4*>(&P[(i0 + a) * 64 + j0]) =
            make_float4(acc[a][0], acc[a][1], acc[a][2], acc[a][3]);
}

// ---------------------------------------------------------------------------
// Kernel 5: reduce sim partials + scale + softmax. grid (64, 16), 64 thr.
// ---------------------------------------------------------------------------
__global__ void __launch_bounds__(64) softmax_kernel()
{
    const int i  = blockIdx.x;
    const int gh = blockIdx.y;
    const int j  = threadIdx.x;

    float v = 0.f;
#pragma unroll
    for (int ks = 0; ks < 4; ++ks)
        v += g_simp[(size_t)(gh * 4 + ks) * 4096 + i * 64 + j];
    v *= 0.125f;

    __shared__ float s[64];
    __shared__ float red;
    s[j] = v;
    __syncthreads();
    if (j == 0) {
        float m = s[0];
        for (int t = 1; t < 64; ++t) m = fmaxf(m, s[t]);
        red = m;
    }
    __syncthreads();
    const float e = __expf(v - red);
    s[j] = e;
    __syncthreads();
    if (j == 0) {
        float su = 0.f;
        for (int t = 0; t < 64; ++t) su += s[t];
        red = su;
    }
    __syncthreads();
    g_attn[(size_t)gh * 4096 + i * 64 + j] = e / red;
}

// ---------------------------------------------------------------------------
// Kernel 6: U = attn @ Wv. grid (4 ftile, 16 gh). 64x64 out, K=64.
// ---------------------------------------------------------------------------
__global__ void __launch_bounds__(256) u_kernel(const float* __restrict__ Wkv)
{
    __shared__ __align__(16) float s_a[64 * FAS];
    __shared__ __align__(16) float s_w[64 * FAS];

    const int ft = blockIdx.x, gh = blockIdx.y;
    const int g = gh >> 3, h = gh & 7;
    const int tid = threadIdx.x;

    const float* A  = g_attn + (size_t)gh * 4096;
    const float* WV = Wkv + (size_t)(512 + h * 64) * 256 + ft * 64;

#pragma unroll
    for (int it = 0; it < 4; ++it) {
        const int idx = tid + it * 256;
        const int row = idx >> 4, c4 = idx & 15;
        *reinterpret_cast<float4*>(&s_a[row * FAS + c4 * 4]) =
            *reinterpret_cast<const float4*>(A + (size_t)row * 64 + c4 * 4);
        *reinterpret_cast<float4*>(&s_w[row * FAS + c4 * 4]) =
            *reinterpret_cast<const float4*>(WV + (size_t)row * 256 + c4 * 4);
    }
    __syncthreads();

    const int i0 = (tid >> 4) * 4, f0 = (tid & 15) * 4;
    float acc[4][4] = {};
#pragma unroll
    for (int j = 0; j < 64; ++j) {
        const float4 wv = *reinterpret_cast<const float4*>(&s_w[j * FAS + f0]);
        float av[4];
#pragma unroll
        for (int a = 0; a < 4; ++a) av[a] = s_a[(i0 + a) * FAS + j];
#pragma unroll
        for (int a = 0; a < 4; ++a) {
            acc[a][0] += av[a] * wv.x; acc[a][1] += av[a] * wv.y;
            acc[a][2] += av[a] * wv.z; acc[a][3] += av[a] * wv.w;
        }
    }

    float* U = g_u + ((size_t)g * 512 + h * 64) * 256 + ft * 64;
#pragma unroll
    for (int a = 0; a < 4; ++a)
        *reinterpret_cast<float4*>(&U[(size_t)(i0 + a) * 256 + f0]) =
            make_float4(acc[a][0], acc[a][1], acc[a][2], acc[a][3]);
}

// ---------------------------------------------------------------------------
// Kernel 7: W2_g = fp16(Wout @ U_g)  (256x256 per group, K=512)
// 4-row tiles, U staged in 32-row chunks with register prefetch. grid (64,2).
// ---------------------------------------------------------------------------
__global__ void __launch_bounds__(256) w2_kernel(const float* __restrict__ Wout)
{
    __shared__ float s_w[4 * 512];
    __shared__ __align__(16) float s_u[32 * 256];

    const int m0 = blockIdx.x * 4, g = blockIdx.y, n = threadIdx.x;
    const float4* Uv = reinterpret_cast<const float4*>(g_u + (size_t)g * 512 * 256);
    float4* su4 = reinterpret_cast<float4*>(s_u);

#pragma unroll
    for (int r = 0; r < 4; ++r) {
        s_w[r * 512 + n]       = Wout[(size_t)(m0 + r) * 512 + n];
        s_w[r * 512 + 256 + n] = Wout[(size_t)(m0 + r) * 512 + 256 + n];
    }

    float4 pre[8];
#pragma unroll
    for (int it = 0; it < 8; ++it)
        pre[it] = Uv[n + it * 256];

    float acc[4] = {};
#pragma unroll 1
    for (int cc = 0; cc < 512; cc += 32) {
        __syncthreads();
#pragma unroll
        for (int it = 0; it < 8; ++it)
            su4[n + it * 256] = pre[it];
        __syncthreads();
        if (cc + 32 < 512) {
            const float4* Un = Uv + (size_t)(cc + 32) * 64;
#pragma unroll
            for (int it = 0; it < 8; ++it)
                pre[it] = Un[n + it * 256];
        }
#pragma unroll
        for (int k = 0; k < 32; ++k) {
            const float uv = s_u[k * 256 + n];
#pragma unroll
            for (int r = 0; r < 4; ++r)
                acc[r] = fmaf(s_w[r * 512 + cc + k], uv, acc[r]);
        }
    }
#pragma unroll
    for (int r = 0; r < 4; ++r)
        g_w2_h[((size_t)g * 256 + m0 + r) * 256 + n] = __float2half_rn(acc[r]);
}

// ---------------------------------------------------------------------------
// Kernel 8: out_g = W2_g @ Xh_g + bout  (1-term). M=256, N=16384, K=256.
// Register-prefetch double buffered.
// ---------------------------------------------------------------------------
__global__ void __launch_bounds__(256) final_kernel(const float* __restrict__ bout,
                                                    float* __restrict__ out)
{
    __shared__ __align__(32) __half sAh[128 * SMS2];
    __shared__ __align__(32) __half sBh[32 * OVS];
    __shared__ __align__(32) float  brep[128 * 16];

    const int tid = threadIdx.x;
    const int wid = tid >> 5;
    const int wm = wid >> 2, wn = wid & 3;
    const int p0 = blockIdx.x * 128;
    const int m0 = blockIdx.y * 128;
    const int g  = blockIdx.z;

    const __half* Ah = g_w2_h + (size_t)g * 65536;
    const __half* Xh = g_xh + (size_t)g * 256 * NSEQ;

    const int arow[2] = { (tid) >> 2, (tid + 256) >> 2 };
    const int ac4     = tid & 3;
    const int brow[2] = { (tid) >> 4, (tid + 256) >> 4 };
    const int bc8     = tid & 15;

    for (int r = tid; r < 128; r += 256) {
        const float bv = bout[m0 + r];
#pragma unroll
        for (int c = 0; c < 16; ++c) brep[r * 16 + c] = bv;
    }
    __syncthreads();

    wmma::fragment<wmma::accumulator, 16, 16, 16, float> acc[4][2];
#pragma unroll
    for (int mi = 0; mi < 4; ++mi)
#pragma unroll
        for (int ni = 0; ni < 2; ++ni)
            wmma::load_matrix_sync(acc[mi][ni],
                                   &brep[(wm * 64 + mi * 16) * 16], 16,
                                   wmma::mem_row_major);

    uint4 rAh[2], rBh[2];
#pragma unroll
    for (int it = 0; it < 2; ++it) {
        const size_t ga = (size_t)(m0 + arow[it]) * 256 + ac4 * 8;
        rAh[it] = *reinterpret_cast<const uint4*>(Ah + ga);
        const size_t gb = (size_t)brow[it] * NSEQ + p0 + bc8 * 8;
        rBh[it] = *reinterpret_cast<const uint4*>(Xh + gb);
    }

#pragma unroll 1
    for (int kk = 0; kk < 256; kk += 32) {
        __syncthreads();
#pragma unroll
        for (int it = 0; it < 2; ++it) {
            const int soA = arow[it] * SMS2 + ac4 * 8;
            *reinterpret_cast<uint4*>(&sAh[soA]) = rAh[it];
            const int soB = brow[it] * OVS + bc8 * 8;
            *reinterpret_cast<uint4*>(&sBh[soB]) = rBh[it];
        }
        __syncthreads();

        if (kk + 32 < 256) {
#pragma unroll
            for (int it = 0; it < 2; ++it) {
                const size_t ga = (size_t)(m0 + arow[it]) * 256 + kk + 32 + ac4 * 8;
                rAh[it] = *reinterpret_cast<const uint4*>(Ah + ga);
                const size_t gb = (size_t)(kk + 32 + brow[it]) * NSEQ + p0 + bc8 * 8;
                rBh[it] = *reinterpret_cast<const uint4*>(Xh + gb);
            }
        }

#pragma unroll
        for (int k2 = 0; k2 < 2; ++k2) {
            wmma::fragment<wmma::matrix_a, 16, 16, 16, __half, wmma::row_major> fah[4];
            wmma::fragment<wmma::matrix_b, 16, 16, 16, __half, wmma::row_major> fbh[2];
#pragma unroll
            for (int mi = 0; mi < 4; ++mi)
                wmma::load_matrix_sync(fah[mi], &sAh[(wm * 64 + mi * 16) * SMS2 + k2 * 16], SMS2);
#pragma unroll
            for (int ni = 0; ni < 2; ++ni)
                wmma::load_matrix_sync(fbh[ni], &sBh[(k2 * 16) * OVS + wn * 32 + ni * 16], OVS);
#pragma unroll
            for (int mi = 0; mi < 4; ++mi)
#pragma unroll
                for (int ni = 0; ni < 2; ++ni)
                    wmma::mma_sync(acc[mi][ni], fah[mi], fbh[ni], acc[mi][ni]);
        }
    }

    float* C = out + (size_t)g * 256 * NSEQ;
#pragma unroll
    for (int mi = 0; mi < 4; ++mi)
#pragma unroll
        for (int ni = 0; ni < 2; ++ni)
            wmma::store_matrix_sync(
                C + (size_t)(m0 + wm * 64 + mi * 16) * NSEQ + p0 + wn * 32 + ni * 16,
                acc[mi][ni], NSEQ, wmma::mem_row_major);
}

// ---------------------------------------------------------------------------
extern "C" void kernel_launch(void* const* d_in, const int* in_sizes, int n_in,
                              void* d_out, int out_size)
{
    const float* x    = (const float*)d_in[0];
    const float* Wq   = (const float*)d_in[1];
    const float* Wkv  = (const float*)d_in[2];
    const float* Wout = (const float*)d_in[3];
    const float* bout = (const float*)d_in[4];
    float* out = (float*)d_out;
    (void)in_sizes; (void)n_in; (void)out_size;

    convert_x   <<<dim3(256, 2), 256>>>(x);
    gram_kernel <<<dim3(GSP, 3, 2), 256>>>();
    gram_reduce <<<dim3(64, 2), 256>>>();
    sq_kernel   <<<dim3(128, 2), 256>>>(Wq);
    simp_kernel <<<dim3(4, 16), 256>>>(Wkv);
    softmax_kernel<<<dim3(64, 16), 64>>>();
    u_kernel    <<<dim3(4, 16), 256>>>(Wkv);
    w2_kernel   <<<dim3(64, 2), 256>>>(Wout);
    final_kernel<<<dim3(NSEQ / 128, 2, 2), 256>>>(bout, out);
}